// round 6
// baseline (speedup 1.0000x reference)
#include <cuda_runtime.h>
#include <cuda_bf16.h>

typedef unsigned long long u64;

#define ATTRC    16
#define RADIALC  8

// ---------------------------------------------------------------------------
// Packed f32x2 helpers (Blackwell)
// ---------------------------------------------------------------------------
__device__ __forceinline__ u64 fma2(u64 a, u64 b, u64 c) {
    u64 d;
    asm("fma.rn.f32x2 %0, %1, %2, %3;" : "=l"(d) : "l"(a), "l"(b), "l"(c));
    return d;
}
__device__ __forceinline__ u64 mul2(u64 a, u64 b) {
    u64 d;
    asm("mul.rn.f32x2 %0, %1, %2;" : "=l"(d) : "l"(a), "l"(b));
    return d;
}
__device__ __forceinline__ u64 splat2(float w) {
    u64 d;
    unsigned int b = __float_as_uint(w);
    asm("mov.b64 %0, {%1, %1};" : "=l"(d) : "r"(b));
    return d;
}
__device__ __forceinline__ float2 unpk(u64 v) {
    unsigned int lo, hi;
    asm("mov.b64 {%0, %1}, %2;" : "=r"(lo), "=r"(hi) : "l"(v));
    return make_float2(__uint_as_float(lo), __uint_as_float(hi));
}

// ---------------------------------------------------------------------------
// Device scratch
// ---------------------------------------------------------------------------
__device__ __align__(16) float g_WE[32768];        // [k=(r*32+u)][wp][4 blocks]
__device__ __align__(16) float g_WS[32768];        // [k2=(u*16+v)][wp][2 paths]
__device__ __align__(16) float g_M[10000 * 128];   // messages

// ---------------------------------------------------------------------------
// Fold kernels.  c_edge = (1/sqrt8)*(1/8)*(1/sqrt32) = 1/128
//                c_node = (1/sqrt512)*(1/sqrt32)     = 1/128
// ---------------------------------------------------------------------------
__global__ void fold_edge_kernel(const float* __restrict__ Wgen,
                                 const float* __restrict__ L1s,
                                 const float* __restrict__ L1v)
{
    int idx = blockIdx.x * blockDim.x + threadIdx.x;   // < 32768
    int b   = idx >> 13;
    int rem = idx & 8191;
    int r   = rem >> 10;
    int u   = (rem >> 5) & 31;
    int wp  = rem & 31;

    const float* wg = Wgen + r * 4096 + b * 1024 + u * 32;
    const float* L  = (b == 1 || b == 2) ? L1v : L1s;

    float acc = 0.f;
#pragma unroll
    for (int w = 0; w < 32; w++) acc = fmaf(wg[w], L[w * 32 + wp], acc);

    float c = 0.0078125f;
    if (b == 3) c *= 0.57735026918962576f;   // fold 1/sqrt(3) of the dot into WD
    g_WE[(r * 32 + u) * 128 + wp * 4 + b] = acc * c;
}

__global__ void fold_node_kernel(const float* __restrict__ WS0,
                                 const float* __restrict__ WS1,
                                 const float* __restrict__ L2s,
                                 const float* __restrict__ L2v)
{
    int idx = blockIdx.x * blockDim.x + threadIdx.x;   // < 32768
    int sb  = idx >> 14;
    int rem = idx & 16383;
    int uv  = rem >> 5;
    int wp  = rem & 31;

    const float* ws = (sb ? WS1 : WS0) + uv * 32;
    const float* L  = sb ? L2v : L2s;

    float acc = 0.f;
#pragma unroll
    for (int w = 0; w < 32; w++) acc = fmaf(ws[w], L[w * 32 + wp], acc);

    g_WS[uv * 64 + wp * 2 + sb] = acc * 0.0078125f;
}

__global__ void zero_m_kernel(int n)
{
    int i = blockIdx.x * blockDim.x + threadIdx.x;
    if (i < n) g_M[i] = 0.f;
}

// ---------------------------------------------------------------------------
// Edge kernel: 512 threads, persistent, 64-edge tiles.
// Staged arrays use row stride 68 floats (16B-aligned rows, limits conflicts).
// ---------------------------------------------------------------------------
#define XROW 68
#define XARR 2176
#define EW_OFF    0                                  // 32768
#define EXS_OFF   32768
#define EXV_OFF(i) (EXS_OFF + XARR * (1 + (i)))
#define EDOT_OFF  (EXS_OFF + XARR * 4)               // 41472
#define EA_OFF(v) (43648 + XARR * (v))               // 5 staged a-arrays, end 54528
#define EEF_OFF   54528                              // [8][64]
#define EYS_OFF   55040                              // [64]
#define EYV_OFF   55104                              // [3][64]
#define ESND_OFF  55296                              // int[64]
#define ERCV_OFF  55360                              // int[64]
#define EDGE_SMEM_FLOATS 55424
#define EDGE_SMEM_BYTES  (EDGE_SMEM_FLOATS * 4)      // 221696 B

__global__ void __launch_bounds__(512, 1)
edge_kernel(const float* __restrict__ node_feats,
            const float* __restrict__ edge_attrs,
            const float* __restrict__ edge_feats,
            const int*   __restrict__ edge_index,
            int E)
{
    extern __shared__ float s[];
    const int tid  = threadIdx.x;
    const int lane = tid & 31;
    const int eo   = tid >> 5;     // warp 0..15
    const int eb   = eo << 2;      // 4 edges per warp

    for (int i = tid; i < 8192; i += 512)
        ((float4*)s)[i] = ((const float4*)g_WE)[i];

    int* sSnd = (int*)&s[ESND_OFF];
    int* sRcv = (int*)&s[ERCV_OFF];

    const int ntiles = (E + 63) >> 6;

    for (int t = blockIdx.x; t < ntiles; t += gridDim.x) {
        const int e0 = t << 6;
        __syncthreads();   // protect smem reuse across tiles

        if (tid < 64) {
            int ge = e0 + tid;
            if (ge < E) {
                sSnd[tid] = edge_index[ge];
                sRcv[tid] = edge_index[E + ge];
                float4 ea = *(const float4*)&edge_attrs[(size_t)ge * 4];
                s[EYS_OFF + tid]       = ea.x;
                s[EYV_OFF + tid]       = ea.y;
                s[EYV_OFF + 64 + tid]  = ea.z;
                s[EYV_OFF + 128 + tid] = ea.w;
            } else {
                sSnd[tid] = 0; sRcv[tid] = -1;
                s[EYS_OFF + tid] = 0.f;
                s[EYV_OFF + tid] = 0.f; s[EYV_OFF + 64 + tid] = 0.f; s[EYV_OFF + 128 + tid] = 0.f;
            }
        }
        {
            int e = tid >> 3, r = tid & 7;
            int ge = e0 + e;
            s[EEF_OFF + r * 64 + e] = (ge < E) ? edge_feats[(size_t)ge * 8 + r] : 0.f;
        }
        __syncthreads();

        // ---- gather sender features (coalesced gmem; transposed to [f][e]) ----
        for (int q = tid; q < 64 * 128; q += 512) {
            int e = q >> 7, f = q & 127;
            float v = node_feats[(size_t)sSnd[e] * 128 + f];
            if (f < 32) {
                s[EXS_OFF + f * XROW + e] = v;
            } else {
                int tt = f - 32;
                int uu = tt / 3;
                int ii = tt - uu * 3;
                s[EXV_OFF(ii) + uu * XROW + e] = v;
            }
        }
        __syncthreads();

        // ---- dot[u][e] = xv . yv (1/sqrt3 folded into WD) ----
        for (int q = tid; q < 2048; q += 512) {
            int u = q >> 6, e = q & 63;
            float d = s[EXV_OFF(0) + u * XROW + e] * s[EYV_OFF + e]
                    + s[EXV_OFF(1) + u * XROW + e] * s[EYV_OFF + 64 + e]
                    + s[EXV_OFF(2) + u * XROW + e] * s[EYV_OFF + 128 + e];
            s[EDOT_OFF + u * XROW + e] = d;
        }

        // acc layout: [out*2 + pair]; outs: 0=A 1=B 2=C0 3=C1 4=C2 5=D
        u64 acc[12];
#pragma unroll
        for (int v = 0; v < 12; v++) acc[v] = 0ull;

#pragma unroll 1
        for (int r = 0; r < 8; r++) {
            __syncthreads();
            // ---- stage a[var][u][e] = ef[r][e] * x[var][u][e]  (f32x2) ----
#pragma unroll
            for (int j = 0; j < 10; j++) {
                int pp  = tid + j * 512;          // < 5120
                int var = pp >> 10;
                int rem = pp & 1023;
                int uu  = rem >> 5;
                int ep  = rem & 31;
                int xo  = uu * XROW + 2 * ep;
                u64 xv  = *(const u64*)&s[EXS_OFF + var * XARR + xo];   // var 0..4 covers xs,xv0..2,dot
                u64 efv = *(const u64*)&s[EEF_OFF + r * 64 + 2 * ep];
                *(u64*)&s[EA_OFF(var) + xo] = mul2(xv, efv);
            }
            __syncthreads();

            const int wbase = (r << 5) * 128 + lane * 4;
#pragma unroll 4
            for (int u = 0; u < 32; u++) {
                float4 wv = *(const float4*)&s[EW_OFF + wbase + u * 128];
                u64 wa = splat2(wv.x), wb = splat2(wv.y),
                    wc = splat2(wv.z), wd = splat2(wv.w);
                int ao = u * XROW + eb;
                ulonglong2 a0 = *(const ulonglong2*)&s[EA_OFF(0) + ao];
                ulonglong2 c0 = *(const ulonglong2*)&s[EA_OFF(1) + ao];
                ulonglong2 c1 = *(const ulonglong2*)&s[EA_OFF(2) + ao];
                ulonglong2 c2 = *(const ulonglong2*)&s[EA_OFF(3) + ao];
                ulonglong2 dd = *(const ulonglong2*)&s[EA_OFF(4) + ao];

                acc[0]  = fma2(a0.x, wa, acc[0]);  acc[1]  = fma2(a0.y, wa, acc[1]);
                acc[2]  = fma2(a0.x, wb, acc[2]);  acc[3]  = fma2(a0.y, wb, acc[3]);
                acc[4]  = fma2(c0.x, wc, acc[4]);  acc[5]  = fma2(c0.y, wc, acc[5]);
                acc[6]  = fma2(c1.x, wc, acc[6]);  acc[7]  = fma2(c1.y, wc, acc[7]);
                acc[8]  = fma2(c2.x, wc, acc[8]);  acc[9]  = fma2(c2.y, wc, acc[9]);
                acc[10] = fma2(dd.x, wd, acc[10]); acc[11] = fma2(dd.y, wd, acc[11]);
            }
        }

        // ---- epilogue + scatter-add ----
#pragma unroll
        for (int p = 0; p < 2; p++) {
            float2 A  = unpk(acc[0 + p]);
            float2 B  = unpk(acc[2 + p]);
            float2 C0 = unpk(acc[4 + p]);
            float2 C1 = unpk(acc[6 + p]);
            float2 C2 = unpk(acc[8 + p]);
            float2 D  = unpk(acc[10 + p]);
#pragma unroll
            for (int h = 0; h < 2; h++) {
                int e = eb + 2 * p + h;
                int recv = sRcv[e];
                if (recv < 0) continue;
                float a  = h ? A.y  : A.x;
                float b  = h ? B.y  : B.x;
                float c0 = h ? C0.y : C0.x;
                float c1 = h ? C1.y : C1.x;
                float c2 = h ? C2.y : C2.x;
                float d  = h ? D.y  : D.x;
                float ysv = s[EYS_OFF + e];
                float yv0 = s[EYV_OFF + e], yv1 = s[EYV_OFF + 64 + e], yv2 = s[EYV_OFF + 128 + e];
                float* dst = g_M + (size_t)recv * 128;
                atomicAdd(dst + lane,              fmaf(a, ysv, d));
                atomicAdd(dst + 32 + lane * 3 + 0, fmaf(b, yv0, c0 * ysv));
                atomicAdd(dst + 32 + lane * 3 + 1, fmaf(b, yv1, c1 * ysv));
                atomicAdd(dst + 32 + lane * 3 + 2, fmaf(b, yv2, c2 * ysv));
            }
        }
    }
}

// ---------------------------------------------------------------------------
// Node kernel: 512 threads, persistent, 64-node tiles, v-outer staging.
//   out[w,e] = M[w,e] + sum_v sum_u WS[u,v,w] * (na[v,e]*M[u,e])
// ---------------------------------------------------------------------------
#define NW_OFF    0                                  // 32768
#define NMS_OFF   32768
#define NMV_OFF(i) (NMS_OFF + XARR * (1 + (i)))
#define NNA_OFF   (NMS_OFF + XARR * 4)               // 41472 [16][68]
#define NC_OFF(v) (42560 + XARR * (v))               // 4 staged c-arrays, end 51264
#define NODE_SMEM_FLOATS 51264
#define NODE_SMEM_BYTES  (NODE_SMEM_FLOATS * 4)      // 205056 B

__global__ void __launch_bounds__(512, 1)
node_kernel(const float* __restrict__ node_attrs,
            float* __restrict__ out,
            int N)
{
    extern __shared__ float s[];
    const int tid  = threadIdx.x;
    const int lane = tid & 31;
    const int eo   = tid >> 5;
    const int eb   = eo << 2;

    for (int i = tid; i < 8192; i += 512)
        ((float4*)s)[i] = ((const float4*)g_WS)[i];

    const int ntiles = (N + 63) >> 6;

    for (int t = blockIdx.x; t < ntiles; t += gridDim.x) {
        const int n0 = t << 6;
        __syncthreads();

        for (int q = tid; q < 64 * 128; q += 512) {
            int e = q >> 7, f = q & 127;
            int n = n0 + e;
            float v = (n < N) ? g_M[(size_t)n * 128 + f] : 0.f;
            if (f < 32) {
                s[NMS_OFF + f * XROW + e] = v;
            } else {
                int tt = f - 32;
                int uu = tt / 3;
                int ii = tt - uu * 3;
                s[NMV_OFF(ii) + uu * XROW + e] = v;
            }
        }
        for (int q = tid; q < 64 * 16; q += 512) {
            int e = q >> 4, v = q & 15;
            int n = n0 + e;
            s[NNA_OFF + v * XROW + e] = (n < N) ? node_attrs[(size_t)n * 16 + v] : 0.f;
        }

        // acc pairs: [0,1]=S [2,3]=V0 [4,5]=V1 [6,7]=V2
        u64 acc[8];
#pragma unroll
        for (int q = 0; q < 8; q++) acc[q] = 0ull;

#pragma unroll 1
        for (int v = 0; v < 16; v++) {
            __syncthreads();
            // ---- stage c[var][u][e] = na[v][e] * M[var][u][e] ----
#pragma unroll
            for (int j = 0; j < 8; j++) {
                int pp  = tid + j * 512;          // < 4096
                int var = pp >> 10;
                int rem = pp & 1023;
                int uu  = rem >> 5;
                int ep  = rem & 31;
                int xo  = uu * XROW + 2 * ep;
                u64 mv  = *(const u64*)&s[NMS_OFF + var * XARR + xo];
                u64 nav = *(const u64*)&s[NNA_OFF + v * XROW + 2 * ep];
                *(u64*)&s[NC_OFF(var) + xo] = mul2(mv, nav);
            }
            __syncthreads();

            const int wbase = v * 64 + lane * 2;
#pragma unroll 4
            for (int u = 0; u < 32; u++) {
                float2 wv = *(const float2*)&s[NW_OFF + wbase + u * 1024];
                u64 w0 = splat2(wv.x), w1 = splat2(wv.y);
                int ao = u * XROW + eb;
                ulonglong2 m0 = *(const ulonglong2*)&s[NC_OFF(0) + ao];
                ulonglong2 m1 = *(const ulonglong2*)&s[NC_OFF(1) + ao];
                ulonglong2 m2 = *(const ulonglong2*)&s[NC_OFF(2) + ao];
                ulonglong2 m3 = *(const ulonglong2*)&s[NC_OFF(3) + ao];

                acc[0] = fma2(m0.x, w0, acc[0]); acc[1] = fma2(m0.y, w0, acc[1]);
                acc[2] = fma2(m1.x, w1, acc[2]); acc[3] = fma2(m1.y, w1, acc[3]);
                acc[4] = fma2(m2.x, w1, acc[4]); acc[5] = fma2(m2.y, w1, acc[5]);
                acc[6] = fma2(m3.x, w1, acc[6]); acc[7] = fma2(m3.y, w1, acc[7]);
            }
        }

        // ---- epilogue: out = M + skip ----
#pragma unroll
        for (int p = 0; p < 2; p++) {
            float2 S  = unpk(acc[0 + p]);
            float2 V0 = unpk(acc[2 + p]);
            float2 V1 = unpk(acc[4 + p]);
            float2 V2 = unpk(acc[6 + p]);
#pragma unroll
            for (int h = 0; h < 2; h++) {
                int e = eb + 2 * p + h;
                int n = n0 + e;
                if (n >= N) continue;
                float* o = out + (size_t)n * 128;
                o[lane]              = s[NMS_OFF    + lane * XROW + e] + (h ? S.y  : S.x);
                o[32 + lane * 3 + 0] = s[NMV_OFF(0) + lane * XROW + e] + (h ? V0.y : V0.x);
                o[32 + lane * 3 + 1] = s[NMV_OFF(1) + lane * XROW + e] + (h ? V1.y : V1.x);
                o[32 + lane * 3 + 2] = s[NMV_OFF(2) + lane * XROW + e] + (h ? V2.y : V2.x);
            }
        }
    }
}

// ---------------------------------------------------------------------------
// Launch
// ---------------------------------------------------------------------------
extern "C" void kernel_launch(void* const* d_in, const int* in_sizes, int n_in,
                              void* d_out, int out_size)
{
    const float* node_attrs = (const float*)d_in[0];
    const float* node_feats = (const float*)d_in[1];
    const float* edge_attrs = (const float*)d_in[2];
    const float* edge_feats = (const float*)d_in[3];
    const int*   edge_index = (const int*)  d_in[4];
    const float* Wgen       = (const float*)d_in[5];
    const float* L1s        = (const float*)d_in[6];
    const float* L1v        = (const float*)d_in[7];
    const float* WS0        = (const float*)d_in[8];
    const float* WS1        = (const float*)d_in[9];
    const float* L2s        = (const float*)d_in[10];
    const float* L2v        = (const float*)d_in[11];
    float* out = (float*)d_out;

    const int N = in_sizes[0] / ATTRC;        // 10000
    const int E = in_sizes[3] / RADIALC;      // 100000

    cudaFuncSetAttribute(edge_kernel, cudaFuncAttributeMaxDynamicSharedMemorySize, EDGE_SMEM_BYTES);
    cudaFuncSetAttribute(node_kernel, cudaFuncAttributeMaxDynamicSharedMemorySize, NODE_SMEM_BYTES);

    fold_edge_kernel<<<64, 512>>>(Wgen, L1s, L1v);
    fold_node_kernel<<<64, 512>>>(WS0, WS1, L2s, L2v);
    zero_m_kernel<<<(N * 128 + 511) / 512, 512>>>(N * 128);
    edge_kernel<<<148, 512, EDGE_SMEM_BYTES>>>(node_feats, edge_attrs, edge_feats, edge_index, E);
    node_kernel<<<148, 512, NODE_SMEM_BYTES>>>(node_attrs, out, N);
}

// round 8
// speedup vs baseline: 1.9085x; 1.9085x over previous
#include <cuda_runtime.h>
#include <cuda_bf16.h>

typedef unsigned long long u64;

#define ATTRC    16
#define RADIALC  8

// ---------------------------------------------------------------------------
// Packed f32x2 helpers (for the node kernel)
// ---------------------------------------------------------------------------
__device__ __forceinline__ u64 fma2(u64 a, u64 b, u64 c) {
    u64 d; asm("fma.rn.f32x2 %0, %1, %2, %3;" : "=l"(d) : "l"(a), "l"(b), "l"(c)); return d;
}
__device__ __forceinline__ u64 mul2(u64 a, u64 b) {
    u64 d; asm("mul.rn.f32x2 %0, %1, %2;" : "=l"(d) : "l"(a), "l"(b)); return d;
}
__device__ __forceinline__ u64 splat2(float w) {
    u64 d; unsigned int b = __float_as_uint(w);
    asm("mov.b64 %0, {%1, %1};" : "=l"(d) : "r"(b)); return d;
}
__device__ __forceinline__ float2 unpk(u64 v) {
    unsigned int lo, hi; asm("mov.b64 {%0, %1}, %2;" : "=r"(lo), "=r"(hi) : "l"(v));
    return make_float2(__uint_as_float(lo), __uint_as_float(hi));
}

// ---------------------------------------------------------------------------
// Device scratch
// ---------------------------------------------------------------------------
__device__ __align__(16) float g_WE[32768];          // [k=(r*32+u)][wp][4 blocks]
__device__ __align__(16) float g_WS[32768];          // [k2=(u*16+v)][wp][2 paths]
__device__ __align__(16) float g_M[10000 * 128];     // messages
__device__ __align__(16) float g_Q[10000 * 2048];    // per-node precomputed Q[n][g][r][w]

// ---------------------------------------------------------------------------
// Fold kernels.  c_edge = (1/sqrt8)*(1/8)*(1/sqrt32) = 1/128
//                c_node = (1/sqrt512)*(1/sqrt32)     = 1/128
// ---------------------------------------------------------------------------
__global__ void fold_edge_kernel(const float* __restrict__ Wgen,
                                 const float* __restrict__ L1s,
                                 const float* __restrict__ L1v)
{
    int idx = blockIdx.x * blockDim.x + threadIdx.x;   // < 32768
    int b   = idx >> 13;            // 0..3 (A,B,C,D)
    int rem = idx & 8191;
    int r   = rem >> 10;
    int u   = (rem >> 5) & 31;
    int wp  = rem & 31;

    const float* wg = Wgen + r * 4096 + b * 1024 + u * 32;
    const float* L  = (b == 1 || b == 2) ? L1v : L1s;

    float acc = 0.f;
#pragma unroll
    for (int w = 0; w < 32; w++) acc = fmaf(wg[w], L[w * 32 + wp], acc);

    float c = 0.0078125f;
    if (b == 3) c *= 0.57735026918962576f;   // fold 1/sqrt(3) of the dot into WD
    g_WE[(r * 32 + u) * 128 + wp * 4 + b] = acc * c;
}

__global__ void fold_node_kernel(const float* __restrict__ WS0,
                                 const float* __restrict__ WS1,
                                 const float* __restrict__ L2s,
                                 const float* __restrict__ L2v)
{
    int idx = blockIdx.x * blockDim.x + threadIdx.x;   // < 32768
    int sb  = idx >> 14;
    int rem = idx & 16383;
    int uv  = rem >> 5;
    int wp  = rem & 31;

    const float* ws = (sb ? WS1 : WS0) + uv * 32;
    const float* L  = sb ? L2v : L2s;

    float acc = 0.f;
#pragma unroll
    for (int w = 0; w < 32; w++) acc = fmaf(ws[w], L[w * 32 + wp], acc);

    g_WS[uv * 64 + wp * 2 + sb] = acc * 0.0078125f;
}

__global__ void zero_m_kernel(int n)
{
    int i = blockIdx.x * blockDim.x + threadIdx.x;
    if (i < n) g_M[i] = 0.f;
}

// ===========================================================================
// Q kernel: per-node precompute.
//   Q[n][g][r][w], g: 0=A(xs) 1=B(xs) 2..4=C_i(xv_i) 5..7=D_i(xv_i)
//   Q[n][g][r][w] = sum_u Wg_folded[r][u][w] * x[n][u]
// 512 threads, persistent, 64-node tiles; warp owns 4 nodes, lane = w.
// ===========================================================================
#define XROW 68
#define XARR 2176
#define QW_OFF 0
#define QX_OFF 32768                      // [var 4][u 32][XROW]
#define Q_SMEM_FLOATS (QX_OFF + 4 * XARR) // 41472
#define Q_SMEM_BYTES  (Q_SMEM_FLOATS * 4) // 165888

__global__ void __launch_bounds__(512, 1)
q_kernel(const float* __restrict__ node_feats, int N)
{
    extern __shared__ float s[];
    const int tid  = threadIdx.x;
    const int lane = tid & 31;
    const int eo   = tid >> 5;
    const int eb   = eo << 2;

    for (int i = tid; i < 8192; i += 512)
        ((float4*)s)[i] = ((const float4*)g_WE)[i];

    const int ntiles = (N + 63) >> 6;

    for (int t = blockIdx.x; t < ntiles; t += gridDim.x) {
        const int n0 = t << 6;
        __syncthreads();

        // ---- stage node features, transposed to [var][u][node] ----
        for (int q = tid; q < 64 * 128; q += 512) {
            int e = q >> 7, f = q & 127;
            int n = n0 + e;
            float v = (n < N) ? node_feats[(size_t)n * 128 + f] : 0.f;
            if (f < 32) {
                s[QX_OFF + f * XROW + e] = v;
            } else {
                int tt = f - 32;
                int uu = tt / 3;
                int ii = tt - uu * 3;
                s[QX_OFF + (1 + ii) * XARR + uu * XROW + e] = v;
            }
        }
        __syncthreads();

#pragma unroll 1
        for (int r = 0; r < 8; r++) {
            float acc[8][4];
#pragma unroll
            for (int g = 0; g < 8; g++)
#pragma unroll
                for (int j = 0; j < 4; j++) acc[g][j] = 0.f;

            const int wbase = (r << 5) * 128 + lane * 4;
#pragma unroll 4
            for (int u = 0; u < 32; u++) {
                float4 wv = *(const float4*)&s[QW_OFF + wbase + u * 128];
                int xo = u * XROW + eb;
                float4 xs = *(const float4*)&s[QX_OFF + 0 * XARR + xo];
                float4 x0 = *(const float4*)&s[QX_OFF + 1 * XARR + xo];
                float4 x1 = *(const float4*)&s[QX_OFF + 2 * XARR + xo];
                float4 x2 = *(const float4*)&s[QX_OFF + 3 * XARR + xo];

                acc[0][0] = fmaf(wv.x, xs.x, acc[0][0]); acc[0][1] = fmaf(wv.x, xs.y, acc[0][1]);
                acc[0][2] = fmaf(wv.x, xs.z, acc[0][2]); acc[0][3] = fmaf(wv.x, xs.w, acc[0][3]);
                acc[1][0] = fmaf(wv.y, xs.x, acc[1][0]); acc[1][1] = fmaf(wv.y, xs.y, acc[1][1]);
                acc[1][2] = fmaf(wv.y, xs.z, acc[1][2]); acc[1][3] = fmaf(wv.y, xs.w, acc[1][3]);
                acc[2][0] = fmaf(wv.z, x0.x, acc[2][0]); acc[2][1] = fmaf(wv.z, x0.y, acc[2][1]);
                acc[2][2] = fmaf(wv.z, x0.z, acc[2][2]); acc[2][3] = fmaf(wv.z, x0.w, acc[2][3]);
                acc[3][0] = fmaf(wv.z, x1.x, acc[3][0]); acc[3][1] = fmaf(wv.z, x1.y, acc[3][1]);
                acc[3][2] = fmaf(wv.z, x1.z, acc[3][2]); acc[3][3] = fmaf(wv.z, x1.w, acc[3][3]);
                acc[4][0] = fmaf(wv.z, x2.x, acc[4][0]); acc[4][1] = fmaf(wv.z, x2.y, acc[4][1]);
                acc[4][2] = fmaf(wv.z, x2.z, acc[4][2]); acc[4][3] = fmaf(wv.z, x2.w, acc[4][3]);
                acc[5][0] = fmaf(wv.w, x0.x, acc[5][0]); acc[5][1] = fmaf(wv.w, x0.y, acc[5][1]);
                acc[5][2] = fmaf(wv.w, x0.z, acc[5][2]); acc[5][3] = fmaf(wv.w, x0.w, acc[5][3]);
                acc[6][0] = fmaf(wv.w, x1.x, acc[6][0]); acc[6][1] = fmaf(wv.w, x1.y, acc[6][1]);
                acc[6][2] = fmaf(wv.w, x1.z, acc[6][2]); acc[6][3] = fmaf(wv.w, x1.w, acc[6][3]);
                acc[7][0] = fmaf(wv.w, x2.x, acc[7][0]); acc[7][1] = fmaf(wv.w, x2.y, acc[7][1]);
                acc[7][2] = fmaf(wv.w, x2.z, acc[7][2]); acc[7][3] = fmaf(wv.w, x2.w, acc[7][3]);
            }

            // coalesced stores: lane = w
#pragma unroll
            for (int j = 0; j < 4; j++) {
                int n = n0 + eb + j;
                if (n >= N) continue;
                float* qn = g_Q + (size_t)n * 2048 + r * 32 + lane;
#pragma unroll
                for (int g = 0; g < 8; g++)
                    qn[g * 256] = acc[g][j];
            }
        }
    }
}

// ===========================================================================
// Edge kernel: warp = edge.  p_g = sum_r ef_r * Q[snd][g][r][lane]
//   ms   = pA*ys + sum_i yv_i*pD_i
//   mv_i = pB*yv_i + pC_i*ys
// ===========================================================================
__global__ void __launch_bounds__(512, 1)
edge_kernel(const float* __restrict__ edge_attrs,
            const float* __restrict__ edge_feats,
            const int*   __restrict__ edge_index,
            int E)
{
    const int lane = threadIdx.x & 31;
    const int wid  = threadIdx.x >> 5;
    const int gw   = blockIdx.x * 16 + wid;
    const int nw   = gridDim.x * 16;

    for (int e = gw; e < E; e += nw) {
        int snd = __ldg(&edge_index[e]);
        int rcv = __ldg(&edge_index[E + e]);
        float4 ea  = *(const float4*)&edge_attrs[(size_t)e * 4];
        float4 ef0 = *(const float4*)&edge_feats[(size_t)e * 8];
        float4 ef1 = *(const float4*)&edge_feats[(size_t)e * 8 + 4];

        const float* Q = g_Q + (size_t)snd * 2048 + lane;
        float p[8];
#pragma unroll
        for (int g = 0; g < 8; g++) {
            const float* q = Q + g * 256;
            float a =        q[0]   * ef0.x;
            a = fmaf(q[32],  ef0.y, a);
            a = fmaf(q[64],  ef0.z, a);
            a = fmaf(q[96],  ef0.w, a);
            a = fmaf(q[128], ef1.x, a);
            a = fmaf(q[160], ef1.y, a);
            a = fmaf(q[192], ef1.z, a);
            a = fmaf(q[224], ef1.w, a);
            p[g] = a;
        }

        // ea.x = ys; ea.y/z/w = yv0/1/2
        float ms = fmaf(p[0], ea.x, fmaf(p[5], ea.y, fmaf(p[6], ea.z, p[7] * ea.w)));
        float* dst = g_M + (size_t)rcv * 128;
        atomicAdd(dst + lane,              ms);
        atomicAdd(dst + 32 + lane * 3 + 0, fmaf(p[1], ea.y, p[2] * ea.x));
        atomicAdd(dst + 32 + lane * 3 + 1, fmaf(p[1], ea.z, p[3] * ea.x));
        atomicAdd(dst + 32 + lane * 3 + 2, fmaf(p[1], ea.w, p[4] * ea.x));
    }
}

// ===========================================================================
// Node kernel (unchanged from R5 — passing)
// ===========================================================================
#define NW_OFF    0
#define NMS_OFF   32768
#define NMV_OFF(i) (NMS_OFF + XARR * (1 + (i)))
#define NNA_OFF   (NMS_OFF + XARR * 4)
#define NC_OFF(v) (42560 + XARR * (v))
#define NODE_SMEM_FLOATS 51264
#define NODE_SMEM_BYTES  (NODE_SMEM_FLOATS * 4)

__global__ void __launch_bounds__(512, 1)
node_kernel(const float* __restrict__ node_attrs,
            float* __restrict__ out,
            int N)
{
    extern __shared__ float s[];
    const int tid  = threadIdx.x;
    const int lane = tid & 31;
    const int eo   = tid >> 5;
    const int eb   = eo << 2;

    for (int i = tid; i < 8192; i += 512)
        ((float4*)s)[i] = ((const float4*)g_WS)[i];

    const int ntiles = (N + 63) >> 6;

    for (int t = blockIdx.x; t < ntiles; t += gridDim.x) {
        const int n0 = t << 6;
        __syncthreads();

        for (int q = tid; q < 64 * 128; q += 512) {
            int e = q >> 7, f = q & 127;
            int n = n0 + e;
            float v = (n < N) ? g_M[(size_t)n * 128 + f] : 0.f;
            if (f < 32) {
                s[NMS_OFF + f * XROW + e] = v;
            } else {
                int tt = f - 32;
                int uu = tt / 3;
                int ii = tt - uu * 3;
                s[NMV_OFF(ii) + uu * XROW + e] = v;
            }
        }
        for (int q = tid; q < 64 * 16; q += 512) {
            int e = q >> 4, v = q & 15;
            int n = n0 + e;
            s[NNA_OFF + v * XROW + e] = (n < N) ? node_attrs[(size_t)n * 16 + v] : 0.f;
        }

        u64 acc[8];
#pragma unroll
        for (int q = 0; q < 8; q++) acc[q] = 0ull;

#pragma unroll 1
        for (int v = 0; v < 16; v++) {
            __syncthreads();
#pragma unroll
            for (int j = 0; j < 8; j++) {
                int pp  = tid + j * 512;
                int var = pp >> 10;
                int rem = pp & 1023;
                int uu  = rem >> 5;
                int ep  = rem & 31;
                int xo  = uu * XROW + 2 * ep;
                u64 mv  = *(const u64*)&s[NMS_OFF + var * XARR + xo];
                u64 nav = *(const u64*)&s[NNA_OFF + v * XROW + 2 * ep];
                *(u64*)&s[NC_OFF(var) + xo] = mul2(mv, nav);
            }
            __syncthreads();

            const int wbase = v * 64 + lane * 2;
#pragma unroll 4
            for (int u = 0; u < 32; u++) {
                float2 wv = *(const float2*)&s[NW_OFF + wbase + u * 1024];
                u64 w0 = splat2(wv.x), w1 = splat2(wv.y);
                int ao = u * XROW + eb;
                ulonglong2 m0 = *(const ulonglong2*)&s[NC_OFF(0) + ao];
                ulonglong2 m1 = *(const ulonglong2*)&s[NC_OFF(1) + ao];
                ulonglong2 m2 = *(const ulonglong2*)&s[NC_OFF(2) + ao];
                ulonglong2 m3 = *(const ulonglong2*)&s[NC_OFF(3) + ao];

                acc[0] = fma2(m0.x, w0, acc[0]); acc[1] = fma2(m0.y, w0, acc[1]);
                acc[2] = fma2(m1.x, w1, acc[2]); acc[3] = fma2(m1.y, w1, acc[3]);
                acc[4] = fma2(m2.x, w1, acc[4]); acc[5] = fma2(m2.y, w1, acc[5]);
                acc[6] = fma2(m3.x, w1, acc[6]); acc[7] = fma2(m3.y, w1, acc[7]);
            }
        }

#pragma unroll
        for (int p = 0; p < 2; p++) {
            float2 S  = unpk(acc[0 + p]);
            float2 V0 = unpk(acc[2 + p]);
            float2 V1 = unpk(acc[4 + p]);
            float2 V2 = unpk(acc[6 + p]);
#pragma unroll
            for (int h = 0; h < 2; h++) {
                int e = eb + 2 * p + h;
                int n = n0 + e;
                if (n >= N) continue;
                float* o = out + (size_t)n * 128;
                o[lane]              = s[NMS_OFF    + lane * XROW + e] + (h ? S.y  : S.x);
                o[32 + lane * 3 + 0] = s[NMV_OFF(0) + lane * XROW + e] + (h ? V0.y : V0.x);
                o[32 + lane * 3 + 1] = s[NMV_OFF(1) + lane * XROW + e] + (h ? V1.y : V1.x);
                o[32 + lane * 3 + 2] = s[NMV_OFF(2) + lane * XROW + e] + (h ? V2.y : V2.x);
            }
        }
    }
}

// ===========================================================================
// Launch
// ===========================================================================
extern "C" void kernel_launch(void* const* d_in, const int* in_sizes, int n_in,
                              void* d_out, int out_size)
{
    const float* node_attrs = (const float*)d_in[0];
    const float* node_feats = (const float*)d_in[1];
    const float* edge_attrs = (const float*)d_in[2];
    const float* edge_feats = (const float*)d_in[3];
    const int*   edge_index = (const int*)  d_in[4];
    const float* Wgen       = (const float*)d_in[5];
    const float* L1s        = (const float*)d_in[6];
    const float* L1v        = (const float*)d_in[7];
    const float* WS0        = (const float*)d_in[8];
    const float* WS1        = (const float*)d_in[9];
    const float* L2s        = (const float*)d_in[10];
    const float* L2v        = (const float*)d_in[11];
    float* out = (float*)d_out;

    const int N = in_sizes[0] / ATTRC;        // 10000
    const int E = in_sizes[3] / RADIALC;      // 100000

    cudaFuncSetAttribute(q_kernel,    cudaFuncAttributeMaxDynamicSharedMemorySize, Q_SMEM_BYTES);
    cudaFuncSetAttribute(node_kernel, cudaFuncAttributeMaxDynamicSharedMemorySize, NODE_SMEM_BYTES);

    fold_edge_kernel<<<64, 512>>>(Wgen, L1s, L1v);
    fold_node_kernel<<<64, 512>>>(WS0, WS1, L2s, L2v);
    zero_m_kernel<<<(N * 128 + 511) / 512, 512>>>(N * 128);
    q_kernel<<<148, 512, Q_SMEM_BYTES>>>(node_feats, N);
    edge_kernel<<<148, 512>>>(edge_attrs, edge_feats, edge_index, E);
    node_kernel<<<148, 512, NODE_SMEM_BYTES>>>(node_attrs, out, N);
}

// round 9
// speedup vs baseline: 2.1570x; 1.1302x over previous
#include <cuda_runtime.h>
#include <cuda_bf16.h>

typedef unsigned long long u64;

#define ATTRC    16
#define RADIALC  8
#define NMAX     10000
#define EMAX     100000

// ---------------------------------------------------------------------------
// Packed f32x2 helpers
// ---------------------------------------------------------------------------
__device__ __forceinline__ u64 fma2(u64 a, u64 b, u64 c) {
    u64 d; asm("fma.rn.f32x2 %0, %1, %2, %3;" : "=l"(d) : "l"(a), "l"(b), "l"(c)); return d;
}
__device__ __forceinline__ u64 mul2(u64 a, u64 b) {
    u64 d; asm("mul.rn.f32x2 %0, %1, %2;" : "=l"(d) : "l"(a), "l"(b)); return d;
}
__device__ __forceinline__ u64 splat2(float w) {
    u64 d; unsigned int b = __float_as_uint(w);
    asm("mov.b64 %0, {%1, %1};" : "=l"(d) : "r"(b)); return d;
}
__device__ __forceinline__ float2 unpk(u64 v) {
    unsigned int lo, hi; asm("mov.b64 {%0, %1}, %2;" : "=r"(lo), "=r"(hi) : "l"(v));
    return make_float2(__uint_as_float(lo), __uint_as_float(hi));
}

// ---------------------------------------------------------------------------
// Device scratch
// ---------------------------------------------------------------------------
__device__ __align__(16) float g_WE[32768];          // [k=(r*32+u)][wp][4 blocks]
__device__ __align__(16) float g_WS[32768];          // [k2=(u*16+v)][wp][2 paths]
__device__ __align__(16) float g_M[NMAX * 128];      // messages
__device__ __align__(16) float g_Q[NMAX * 2048];     // Q[n][g][r][w]
__device__ int g_cnt[NMAX];                          // sender histogram
__device__ int g_startArr[NMAX + 1];                 // CSR offsets
__device__ int g_cur[NMAX];                          // scatter cursors
__device__ int g_eidx[EMAX];                         // edge ids grouped by sender

// ---------------------------------------------------------------------------
// Fold kernels.  c_edge = c_node = 1/128
// ---------------------------------------------------------------------------
__global__ void fold_edge_kernel(const float* __restrict__ Wgen,
                                 const float* __restrict__ L1s,
                                 const float* __restrict__ L1v)
{
    int idx = blockIdx.x * blockDim.x + threadIdx.x;   // < 32768
    int b   = idx >> 13;
    int rem = idx & 8191;
    int r   = rem >> 10;
    int u   = (rem >> 5) & 31;
    int wp  = rem & 31;

    const float* wg = Wgen + r * 4096 + b * 1024 + u * 32;
    const float* L  = (b == 1 || b == 2) ? L1v : L1s;

    float acc = 0.f;
#pragma unroll
    for (int w = 0; w < 32; w++) acc = fmaf(wg[w], L[w * 32 + wp], acc);

    float c = 0.0078125f;
    if (b == 3) c *= 0.57735026918962576f;   // fold 1/sqrt(3) into WD
    g_WE[(r * 32 + u) * 128 + wp * 4 + b] = acc * c;
}

__global__ void fold_node_kernel(const float* __restrict__ WS0,
                                 const float* __restrict__ WS1,
                                 const float* __restrict__ L2s,
                                 const float* __restrict__ L2v)
{
    int idx = blockIdx.x * blockDim.x + threadIdx.x;   // < 32768
    int sb  = idx >> 14;
    int rem = idx & 16383;
    int uv  = rem >> 5;
    int wp  = rem & 31;

    const float* ws = (sb ? WS1 : WS0) + uv * 32;
    const float* L  = sb ? L2v : L2s;

    float acc = 0.f;
#pragma unroll
    for (int w = 0; w < 32; w++) acc = fmaf(ws[w], L[w * 32 + wp], acc);

    g_WS[uv * 64 + wp * 2 + sb] = acc * 0.0078125f;
}

// ---------------------------------------------------------------------------
// CSR build
// ---------------------------------------------------------------------------
__global__ void zero_kernel(int nM, int N)
{
    int i = blockIdx.x * blockDim.x + threadIdx.x;
    if (i < nM) g_M[i] = 0.f;
    if (i < N)  g_cnt[i] = 0;
}

__global__ void hist_kernel(const int* __restrict__ edge_index, int E)
{
    int e = blockIdx.x * blockDim.x + threadIdx.x;
    if (e < E) atomicAdd(&g_cnt[edge_index[e]], 1);
}

__global__ void scan_kernel(int N)   // single block, 1024 threads
{
    __shared__ int sh[1024];
    __shared__ int carry;
    int tid = threadIdx.x;
    if (tid == 0) carry = 0;
    __syncthreads();
    for (int base = 0; base < N; base += 1024) {
        int v = (base + tid < N) ? g_cnt[base + tid] : 0;
        sh[tid] = v;
        __syncthreads();
#pragma unroll
        for (int off = 1; off < 1024; off <<= 1) {
            int t = (tid >= off) ? sh[tid - off] : 0;
            __syncthreads();
            sh[tid] += t;
            __syncthreads();
        }
        int c = carry;
        if (base + tid < N) {
            int st = c + sh[tid] - v;
            g_startArr[base + tid] = st;
            g_cur[base + tid]      = st;
        }
        __syncthreads();
        if (tid == 1023) carry = c + sh[1023];
        __syncthreads();
    }
    if (tid == 0) g_startArr[N] = carry;
}

__global__ void scatter_kernel(const int* __restrict__ edge_index, int E)
{
    int e = blockIdx.x * blockDim.x + threadIdx.x;
    if (e < E) {
        int pos = atomicAdd(&g_cur[edge_index[e]], 1);
        g_eidx[pos] = e;
    }
}

// ===========================================================================
// Q kernel: Q[n][g][r][w] = sum_u Wg[r][u][w] * x[n][u]   (f32x2 inner loop)
// g: 0=A(xs) 1=B(xs) 2..4=C_i(xv_i) 5..7=D_i(xv_i)
// 512 threads, persistent, 64-node tiles; warp: 4 nodes (2 pairs), lane = w.
// ===========================================================================
#define XROW 68
#define XARR 2176
#define QW_OFF 0
#define QX_OFF 32768                      // [var 4][u 32][XROW]
#define Q_SMEM_FLOATS (QX_OFF + 4 * XARR)
#define Q_SMEM_BYTES  (Q_SMEM_FLOATS * 4)

__global__ void __launch_bounds__(512, 1)
q_kernel(const float* __restrict__ node_feats, int N)
{
    extern __shared__ float s[];
    const int tid  = threadIdx.x;
    const int lane = tid & 31;
    const int eo   = tid >> 5;
    const int eb   = eo << 2;

    for (int i = tid; i < 8192; i += 512)
        ((float4*)s)[i] = ((const float4*)g_WE)[i];

    const int ntiles = (N + 63) >> 6;

    for (int t = blockIdx.x; t < ntiles; t += gridDim.x) {
        const int n0 = t << 6;
        __syncthreads();

        // stage node features, transposed to [var][u][node]
        for (int q = tid; q < 64 * 128; q += 512) {
            int e = q >> 7, f = q & 127;
            int n = n0 + e;
            float v = (n < N) ? node_feats[(size_t)n * 128 + f] : 0.f;
            if (f < 32) {
                s[QX_OFF + f * XROW + e] = v;
            } else {
                int tt = f - 32;
                int uu = tt / 3;
                int ii = tt - uu * 3;
                s[QX_OFF + (1 + ii) * XARR + uu * XROW + e] = v;
            }
        }
        __syncthreads();

#pragma unroll 1
        for (int r = 0; r < 8; r++) {
            u64 acc[8][2];
#pragma unroll
            for (int g = 0; g < 8; g++) { acc[g][0] = 0ull; acc[g][1] = 0ull; }

            const int wbase = (r << 5) * 128 + lane * 4;
#pragma unroll 4
            for (int u = 0; u < 32; u++) {
                float4 wv = *(const float4*)&s[QW_OFF + wbase + u * 128];
                u64 wa = splat2(wv.x), wb = splat2(wv.y),
                    wc = splat2(wv.z), wd = splat2(wv.w);
                int xo = u * XROW + eb;
                ulonglong2 xs = *(const ulonglong2*)&s[QX_OFF + 0 * XARR + xo];
                ulonglong2 x0 = *(const ulonglong2*)&s[QX_OFF + 1 * XARR + xo];
                ulonglong2 x1 = *(const ulonglong2*)&s[QX_OFF + 2 * XARR + xo];
                ulonglong2 x2 = *(const ulonglong2*)&s[QX_OFF + 3 * XARR + xo];

                acc[0][0] = fma2(xs.x, wa, acc[0][0]); acc[0][1] = fma2(xs.y, wa, acc[0][1]);
                acc[1][0] = fma2(xs.x, wb, acc[1][0]); acc[1][1] = fma2(xs.y, wb, acc[1][1]);
                acc[2][0] = fma2(x0.x, wc, acc[2][0]); acc[2][1] = fma2(x0.y, wc, acc[2][1]);
                acc[3][0] = fma2(x1.x, wc, acc[3][0]); acc[3][1] = fma2(x1.y, wc, acc[3][1]);
                acc[4][0] = fma2(x2.x, wc, acc[4][0]); acc[4][1] = fma2(x2.y, wc, acc[4][1]);
                acc[5][0] = fma2(x0.x, wd, acc[5][0]); acc[5][1] = fma2(x0.y, wd, acc[5][1]);
                acc[6][0] = fma2(x1.x, wd, acc[6][0]); acc[6][1] = fma2(x1.y, wd, acc[6][1]);
                acc[7][0] = fma2(x2.x, wd, acc[7][0]); acc[7][1] = fma2(x2.y, wd, acc[7][1]);
            }

            // coalesced stores: lane = w
#pragma unroll
            for (int p = 0; p < 2; p++) {
#pragma unroll
                for (int h = 0; h < 2; h++) {
                    int j = p * 2 + h;
                    int n = n0 + eb + j;
                    if (n >= N) continue;
                    float* qn = g_Q + (size_t)n * 2048 + r * 32 + lane;
#pragma unroll
                    for (int g = 0; g < 8; g++) {
                        float2 f2 = unpk(acc[g][p]);
                        qn[g * 256] = h ? f2.y : f2.x;
                    }
                }
            }
        }
    }
}

// ===========================================================================
// Edge kernel (CSR): warp per sender; Q row held in registers.
//   p_g = sum_r ef_r * Q[snd][g][r][lane]
//   ms   = pA*ys + sum_i yv_i*pD_i ;  mv_i = pB*yv_i + pC_i*ys
// ===========================================================================
__global__ void __launch_bounds__(512, 1)
edge_kernel(const float* __restrict__ edge_attrs,
            const float* __restrict__ edge_feats,
            const int*   __restrict__ edge_index,
            int E, int N)
{
    const int lane = threadIdx.x & 31;
    const int wid  = threadIdx.x >> 5;
    const int gw   = blockIdx.x * 16 + wid;
    const int nw   = gridDim.x * 16;

    for (int n = gw; n < N; n += nw) {
        int s0 = g_startArr[n];
        int s1 = g_startArr[n + 1];
        if (s0 == s1) continue;

        // load Q row: q[g][r], coalesced across lanes
        const float* Qn = g_Q + (size_t)n * 2048 + lane;
        float q[8][8];
#pragma unroll
        for (int g = 0; g < 8; g++)
#pragma unroll
            for (int r = 0; r < 8; r++)
                q[g][r] = Qn[g * 256 + r * 32];

        for (int idx = s0; idx < s1; idx++) {
            int e = __ldg(&g_eidx[idx]);
            int rcv = __ldg(&edge_index[E + e]);
            float4 ea  = *(const float4*)&edge_attrs[(size_t)e * 4];
            float4 ef0 = *(const float4*)&edge_feats[(size_t)e * 8];
            float4 ef1 = *(const float4*)&edge_feats[(size_t)e * 8 + 4];

            float p[8];
#pragma unroll
            for (int g = 0; g < 8; g++) {
                float a =        q[g][0] * ef0.x;
                a = fmaf(q[g][1], ef0.y, a);
                a = fmaf(q[g][2], ef0.z, a);
                a = fmaf(q[g][3], ef0.w, a);
                a = fmaf(q[g][4], ef1.x, a);
                a = fmaf(q[g][5], ef1.y, a);
                a = fmaf(q[g][6], ef1.z, a);
                a = fmaf(q[g][7], ef1.w, a);
                p[g] = a;
            }

            float ms = fmaf(p[0], ea.x, fmaf(p[5], ea.y, fmaf(p[6], ea.z, p[7] * ea.w)));
            float* dst = g_M + (size_t)rcv * 128;
            atomicAdd(dst + lane,              ms);
            atomicAdd(dst + 32 + lane * 3 + 0, fmaf(p[1], ea.y, p[2] * ea.x));
            atomicAdd(dst + 32 + lane * 3 + 1, fmaf(p[1], ea.z, p[3] * ea.x));
            atomicAdd(dst + 32 + lane * 3 + 2, fmaf(p[1], ea.w, p[4] * ea.x));
        }
    }
}

// ===========================================================================
// Node kernel (unchanged — passing)
// ===========================================================================
#define NW_OFF    0
#define NMS_OFF   32768
#define NMV_OFF(i) (NMS_OFF + XARR * (1 + (i)))
#define NNA_OFF   (NMS_OFF + XARR * 4)
#define NC_OFF(v) (42560 + XARR * (v))
#define NODE_SMEM_FLOATS 51264
#define NODE_SMEM_BYTES  (NODE_SMEM_FLOATS * 4)

__global__ void __launch_bounds__(512, 1)
node_kernel(const float* __restrict__ node_attrs,
            float* __restrict__ out,
            int N)
{
    extern __shared__ float s[];
    const int tid  = threadIdx.x;
    const int lane = tid & 31;
    const int eo   = tid >> 5;
    const int eb   = eo << 2;

    for (int i = tid; i < 8192; i += 512)
        ((float4*)s)[i] = ((const float4*)g_WS)[i];

    const int ntiles = (N + 63) >> 6;

    for (int t = blockIdx.x; t < ntiles; t += gridDim.x) {
        const int n0 = t << 6;
        __syncthreads();

        for (int q = tid; q < 64 * 128; q += 512) {
            int e = q >> 7, f = q & 127;
            int n = n0 + e;
            float v = (n < N) ? g_M[(size_t)n * 128 + f] : 0.f;
            if (f < 32) {
                s[NMS_OFF + f * XROW + e] = v;
            } else {
                int tt = f - 32;
                int uu = tt / 3;
                int ii = tt - uu * 3;
                s[NMV_OFF(ii) + uu * XROW + e] = v;
            }
        }
        for (int q = tid; q < 64 * 16; q += 512) {
            int e = q >> 4, v = q & 15;
            int n = n0 + e;
            s[NNA_OFF + v * XROW + e] = (n < N) ? node_attrs[(size_t)n * 16 + v] : 0.f;
        }

        u64 acc[8];
#pragma unroll
        for (int q = 0; q < 8; q++) acc[q] = 0ull;

#pragma unroll 1
        for (int v = 0; v < 16; v++) {
            __syncthreads();
#pragma unroll
            for (int j = 0; j < 8; j++) {
                int pp  = tid + j * 512;
                int var = pp >> 10;
                int rem = pp & 1023;
                int uu  = rem >> 5;
                int ep  = rem & 31;
                int xo  = uu * XROW + 2 * ep;
                u64 mv  = *(const u64*)&s[NMS_OFF + var * XARR + xo];
                u64 nav = *(const u64*)&s[NNA_OFF + v * XROW + 2 * ep];
                *(u64*)&s[NC_OFF(var) + xo] = mul2(mv, nav);
            }
            __syncthreads();

            const int wbase = v * 64 + lane * 2;
#pragma unroll 4
            for (int u = 0; u < 32; u++) {
                float2 wv = *(const float2*)&s[NW_OFF + wbase + u * 1024];
                u64 w0 = splat2(wv.x), w1 = splat2(wv.y);
                int ao = u * XROW + eb;
                ulonglong2 m0 = *(const ulonglong2*)&s[NC_OFF(0) + ao];
                ulonglong2 m1 = *(const ulonglong2*)&s[NC_OFF(1) + ao];
                ulonglong2 m2 = *(const ulonglong2*)&s[NC_OFF(2) + ao];
                ulonglong2 m3 = *(const ulonglong2*)&s[NC_OFF(3) + ao];

                acc[0] = fma2(m0.x, w0, acc[0]); acc[1] = fma2(m0.y, w0, acc[1]);
                acc[2] = fma2(m1.x, w1, acc[2]); acc[3] = fma2(m1.y, w1, acc[3]);
                acc[4] = fma2(m2.x, w1, acc[4]); acc[5] = fma2(m2.y, w1, acc[5]);
                acc[6] = fma2(m3.x, w1, acc[6]); acc[7] = fma2(m3.y, w1, acc[7]);
            }
        }

#pragma unroll
        for (int p = 0; p < 2; p++) {
            float2 S  = unpk(acc[0 + p]);
            float2 V0 = unpk(acc[2 + p]);
            float2 V1 = unpk(acc[4 + p]);
            float2 V2 = unpk(acc[6 + p]);
#pragma unroll
            for (int h = 0; h < 2; h++) {
                int e = eb + 2 * p + h;
                int n = n0 + e;
                if (n >= N) continue;
                float* o = out + (size_t)n * 128;
                o[lane]              = s[NMS_OFF    + lane * XROW + e] + (h ? S.y  : S.x);
                o[32 + lane * 3 + 0] = s[NMV_OFF(0) + lane * XROW + e] + (h ? V0.y : V0.x);
                o[32 + lane * 3 + 1] = s[NMV_OFF(1) + lane * XROW + e] + (h ? V1.y : V1.x);
                o[32 + lane * 3 + 2] = s[NMV_OFF(2) + lane * XROW + e] + (h ? V2.y : V2.x);
            }
        }
    }
}

// ===========================================================================
// Launch
// ===========================================================================
extern "C" void kernel_launch(void* const* d_in, const int* in_sizes, int n_in,
                              void* d_out, int out_size)
{
    const float* node_attrs = (const float*)d_in[0];
    const float* node_feats = (const float*)d_in[1];
    const float* edge_attrs = (const float*)d_in[2];
    const float* edge_feats = (const float*)d_in[3];
    const int*   edge_index = (const int*)  d_in[4];
    const float* Wgen       = (const float*)d_in[5];
    const float* L1s        = (const float*)d_in[6];
    const float* L1v        = (const float*)d_in[7];
    const float* WS0        = (const float*)d_in[8];
    const float* WS1        = (const float*)d_in[9];
    const float* L2s        = (const float*)d_in[10];
    const float* L2v        = (const float*)d_in[11];
    float* out = (float*)d_out;

    const int N = in_sizes[0] / ATTRC;        // 10000
    const int E = in_sizes[3] / RADIALC;      // 100000

    cudaFuncSetAttribute(q_kernel,    cudaFuncAttributeMaxDynamicSharedMemorySize, Q_SMEM_BYTES);
    cudaFuncSetAttribute(node_kernel, cudaFuncAttributeMaxDynamicSharedMemorySize, NODE_SMEM_BYTES);

    fold_edge_kernel<<<64, 512>>>(Wgen, L1s, L1v);
    fold_node_kernel<<<64, 512>>>(WS0, WS1, L2s, L2v);
    zero_kernel<<<(N * 128 + 511) / 512, 512>>>(N * 128, N);
    hist_kernel<<<(E + 511) / 512, 512>>>(edge_index, E);
    scan_kernel<<<1, 1024>>>(N);
    scatter_kernel<<<(E + 511) / 512, 512>>>(edge_index, E);
    q_kernel<<<148, 512, Q_SMEM_BYTES>>>(node_feats, N);
    edge_kernel<<<148, 512>>>(edge_attrs, edge_feats, edge_index, E, N);
    node_kernel<<<148, 512, NODE_SMEM_BYTES>>>(node_attrs, out, N);
}

// round 10
// speedup vs baseline: 3.1689x; 1.4691x over previous
#include <cuda_runtime.h>
#include <cuda_bf16.h>

typedef unsigned long long u64;

#define ATTRC    16
#define RADIALC  8
#define NMAX     10000
#define EMAX     100000

// ---------------------------------------------------------------------------
// Packed f32x2 helpers
// ---------------------------------------------------------------------------
__device__ __forceinline__ u64 fma2(u64 a, u64 b, u64 c) {
    u64 d; asm("fma.rn.f32x2 %0, %1, %2, %3;" : "=l"(d) : "l"(a), "l"(b), "l"(c)); return d;
}
__device__ __forceinline__ u64 splat2(float w) {
    u64 d; unsigned int b = __float_as_uint(w);
    asm("mov.b64 %0, {%1, %1};" : "=l"(d) : "r"(b)); return d;
}
__device__ __forceinline__ float2 unpk(u64 v) {
    unsigned int lo, hi; asm("mov.b64 {%0, %1}, %2;" : "=r"(lo), "=r"(hi) : "l"(v));
    return make_float2(__uint_as_float(lo), __uint_as_float(hi));
}
__device__ __forceinline__ void red_v4(float* p, float a, float b, float c, float d) {
    asm volatile("red.global.add.v4.f32 [%0], {%1, %2, %3, %4};"
                 :: "l"(p), "f"(a), "f"(b), "f"(c), "f"(d) : "memory");
}

// ---------------------------------------------------------------------------
// Device scratch
// ---------------------------------------------------------------------------
__device__ __align__(16) float g_WE[32768];          // [k=(r*32+u)][wp][4 blocks]
__device__ __align__(16) float g_WS[32768];          // [k2=(u*16+v)][wp][2 paths]
__device__ __align__(16) float g_M[NMAX * 128];      // messages [n][lane][4]=(ms,mv0,mv1,mv2)
__device__ __align__(16) float g_Q[NMAX * 2048];     // Q[n][g][r][w]
__device__ int g_cnt[NMAX];
__device__ int g_startArr[NMAX + 1];
__device__ int g_cur[NMAX];
__device__ int g_eidx[EMAX];

// ---------------------------------------------------------------------------
// Prep kernel: fold both weight sets + zero M + zero cnt, one launch.
//   c_edge = c_node = 1/128
// ---------------------------------------------------------------------------
__global__ void prep_kernel(const float* __restrict__ Wgen,
                            const float* __restrict__ L1s,
                            const float* __restrict__ L1v,
                            const float* __restrict__ WS0,
                            const float* __restrict__ WS1,
                            const float* __restrict__ L2s,
                            const float* __restrict__ L2v,
                            int nM, int N)
{
    int i = blockIdx.x * blockDim.x + threadIdx.x;
    if (i < nM) g_M[i] = 0.f;
    if (i < N)  g_cnt[i] = 0;

    if (i < 32768) {
        // fold edge weights
        {
            int b   = i >> 13;
            int rem = i & 8191;
            int r   = rem >> 10;
            int u   = (rem >> 5) & 31;
            int wp  = rem & 31;
            const float* wg = Wgen + r * 4096 + b * 1024 + u * 32;
            const float* L  = (b == 1 || b == 2) ? L1v : L1s;
            float acc = 0.f;
#pragma unroll
            for (int w = 0; w < 32; w++) acc = fmaf(wg[w], L[w * 32 + wp], acc);
            float c = 0.0078125f;
            if (b == 3) c *= 0.57735026918962576f;   // fold 1/sqrt(3) into WD
            g_WE[(r * 32 + u) * 128 + wp * 4 + b] = acc * c;
        }
        // fold node weights
        {
            int sb  = i >> 14;
            int rem = i & 16383;
            int uv  = rem >> 5;
            int wp  = rem & 31;
            const float* ws = (sb ? WS1 : WS0) + uv * 32;
            const float* L  = sb ? L2v : L2s;
            float acc = 0.f;
#pragma unroll
            for (int w = 0; w < 32; w++) acc = fmaf(ws[w], L[w * 32 + wp], acc);
            g_WS[uv * 64 + wp * 2 + sb] = acc * 0.0078125f;
        }
    }
}

// ---------------------------------------------------------------------------
// CSR build
// ---------------------------------------------------------------------------
__global__ void hist_kernel(const int* __restrict__ edge_index, int E)
{
    int e = blockIdx.x * blockDim.x + threadIdx.x;
    if (e < E) atomicAdd(&g_cnt[edge_index[e]], 1);
}

__global__ void scan_kernel(int N)   // single block, 1024 threads
{
    __shared__ int sh[1024];
    __shared__ int carry;
    int tid = threadIdx.x;
    if (tid == 0) carry = 0;
    __syncthreads();
    for (int base = 0; base < N; base += 1024) {
        int v = (base + tid < N) ? g_cnt[base + tid] : 0;
        sh[tid] = v;
        __syncthreads();
#pragma unroll
        for (int off = 1; off < 1024; off <<= 1) {
            int t = (tid >= off) ? sh[tid - off] : 0;
            __syncthreads();
            sh[tid] += t;
            __syncthreads();
        }
        int c = carry;
        if (base + tid < N) {
            int st = c + sh[tid] - v;
            g_startArr[base + tid] = st;
            g_cur[base + tid]      = st;
        }
        __syncthreads();
        if (tid == 1023) carry = c + sh[1023];
        __syncthreads();
    }
    if (tid == 0) g_startArr[N] = carry;
}

__global__ void scatter_kernel(const int* __restrict__ edge_index, int E)
{
    int e = blockIdx.x * blockDim.x + threadIdx.x;
    if (e < E) {
        int pos = atomicAdd(&g_cur[edge_index[e]], 1);
        g_eidx[pos] = e;
    }
}

// ===========================================================================
// Q kernel: Q[n][g][r][w] = sum_u Wg[r][u][w] * x[n][u]
// g: 0=A(xs) 1=B(xs) 2..4=C_i(xv_i) 5..7=D_i(xv_i)
// 544 threads (17 warps x 4 nodes), 68-node tiles -> 148 tiles = 1 wave.
// ===========================================================================
#define QTILE 68
#define QROW  68
#define QARR  2176                      // 32*68
#define QW_OFF 0
#define QX_OFF 32768                    // [var 4][u 32][QROW]
#define Q_SMEM_FLOATS (QX_OFF + 4 * QARR)
#define Q_SMEM_BYTES  (Q_SMEM_FLOATS * 4)

__global__ void __launch_bounds__(544, 1)
q_kernel(const float* __restrict__ node_feats, int N)
{
    extern __shared__ float s[];
    const int tid  = threadIdx.x;
    const int lane = tid & 31;
    const int eo   = tid >> 5;      // 0..16
    const int eb   = eo << 2;       // 0..64

    for (int i = tid; i < 8192; i += 544)
        ((float4*)s)[i] = ((const float4*)g_WE)[i];

    const int ntiles = (N + QTILE - 1) / QTILE;

    for (int t = blockIdx.x; t < ntiles; t += gridDim.x) {
        const int n0 = t * QTILE;
        __syncthreads();

        // stage node features transposed to [var][u][node]
        for (int q = tid; q < QTILE * 128; q += 544) {
            int e = q >> 7, f = q & 127;
            int n = n0 + e;
            float v = (n < N) ? node_feats[(size_t)n * 128 + f] : 0.f;
            if (f < 32) {
                s[QX_OFF + f * QROW + e] = v;
            } else {
                int tt = f - 32;
                int uu = tt / 3;
                int ii = tt - uu * 3;
                s[QX_OFF + (1 + ii) * QARR + uu * QROW + e] = v;
            }
        }
        __syncthreads();

#pragma unroll 1
        for (int r = 0; r < 8; r++) {
            u64 acc[8][2];
#pragma unroll
            for (int g = 0; g < 8; g++) { acc[g][0] = 0ull; acc[g][1] = 0ull; }

            const int wbase = (r << 5) * 128 + lane * 4;
#pragma unroll 4
            for (int u = 0; u < 32; u++) {
                float4 wv = *(const float4*)&s[QW_OFF + wbase + u * 128];
                u64 wa = splat2(wv.x), wb = splat2(wv.y),
                    wc = splat2(wv.z), wd = splat2(wv.w);
                int xo = u * QROW + eb;
                ulonglong2 xs = *(const ulonglong2*)&s[QX_OFF + 0 * QARR + xo];
                ulonglong2 x0 = *(const ulonglong2*)&s[QX_OFF + 1 * QARR + xo];
                ulonglong2 x1 = *(const ulonglong2*)&s[QX_OFF + 2 * QARR + xo];
                ulonglong2 x2 = *(const ulonglong2*)&s[QX_OFF + 3 * QARR + xo];

                acc[0][0] = fma2(xs.x, wa, acc[0][0]); acc[0][1] = fma2(xs.y, wa, acc[0][1]);
                acc[1][0] = fma2(xs.x, wb, acc[1][0]); acc[1][1] = fma2(xs.y, wb, acc[1][1]);
                acc[2][0] = fma2(x0.x, wc, acc[2][0]); acc[2][1] = fma2(x0.y, wc, acc[2][1]);
                acc[3][0] = fma2(x1.x, wc, acc[3][0]); acc[3][1] = fma2(x1.y, wc, acc[3][1]);
                acc[4][0] = fma2(x2.x, wc, acc[4][0]); acc[4][1] = fma2(x2.y, wc, acc[4][1]);
                acc[5][0] = fma2(x0.x, wd, acc[5][0]); acc[5][1] = fma2(x0.y, wd, acc[5][1]);
                acc[6][0] = fma2(x1.x, wd, acc[6][0]); acc[6][1] = fma2(x1.y, wd, acc[6][1]);
                acc[7][0] = fma2(x2.x, wd, acc[7][0]); acc[7][1] = fma2(x2.y, wd, acc[7][1]);
            }

#pragma unroll
            for (int p = 0; p < 2; p++) {
#pragma unroll
                for (int h = 0; h < 2; h++) {
                    int n = n0 + eb + p * 2 + h;
                    if (n >= N) continue;
                    float* qn = g_Q + (size_t)n * 2048 + r * 32 + lane;
#pragma unroll
                    for (int g = 0; g < 8; g++) {
                        float2 f2 = unpk(acc[g][p]);
                        qn[g * 256] = h ? f2.y : f2.x;
                    }
                }
            }
        }
    }
}

// ===========================================================================
// Edge kernel (CSR): warp per sender; Q row in registers; v4 red scatter.
// ===========================================================================
__global__ void __launch_bounds__(512, 1)
edge_kernel(const float* __restrict__ edge_attrs,
            const float* __restrict__ edge_feats,
            const int*   __restrict__ edge_index,
            int E, int N)
{
    const int lane = threadIdx.x & 31;
    const int wid  = threadIdx.x >> 5;
    const int gw   = blockIdx.x * 16 + wid;
    const int nw   = gridDim.x * 16;

    for (int n = gw; n < N; n += nw) {
        int s0 = g_startArr[n];
        int s1 = g_startArr[n + 1];
        if (s0 == s1) continue;

        const float* Qn = g_Q + (size_t)n * 2048 + lane;
        float q[8][8];
#pragma unroll
        for (int g = 0; g < 8; g++)
#pragma unroll
            for (int r = 0; r < 8; r++)
                q[g][r] = Qn[g * 256 + r * 32];

        for (int idx = s0; idx < s1; idx++) {
            int e = __ldg(&g_eidx[idx]);
            int rcv = __ldg(&edge_index[E + e]);
            float4 ea  = *(const float4*)&edge_attrs[(size_t)e * 4];
            float4 ef0 = *(const float4*)&edge_feats[(size_t)e * 8];
            float4 ef1 = *(const float4*)&edge_feats[(size_t)e * 8 + 4];

            float p[8];
#pragma unroll
            for (int g = 0; g < 8; g++) {
                float a =        q[g][0] * ef0.x;
                a = fmaf(q[g][1], ef0.y, a);
                a = fmaf(q[g][2], ef0.z, a);
                a = fmaf(q[g][3], ef0.w, a);
                a = fmaf(q[g][4], ef1.x, a);
                a = fmaf(q[g][5], ef1.y, a);
                a = fmaf(q[g][6], ef1.z, a);
                a = fmaf(q[g][7], ef1.w, a);
                p[g] = a;
            }

            float ms  = fmaf(p[0], ea.x, fmaf(p[5], ea.y, fmaf(p[6], ea.z, p[7] * ea.w)));
            float mv0 = fmaf(p[1], ea.y, p[2] * ea.x);
            float mv1 = fmaf(p[1], ea.z, p[3] * ea.x);
            float mv2 = fmaf(p[1], ea.w, p[4] * ea.x);

            red_v4(g_M + (size_t)rcv * 128 + lane * 4, ms, mv0, mv1, mv2);
        }
    }
}

// ===========================================================================
// Node kernel v2: 544 threads, 68-node tiles (1 wave), part-register scheme.
//   out[w,e] = M[w,e] + sum_v na[v,e] * (sum_u WS[u,v,w] M[u,e])
// ===========================================================================
#define NROW  68
#define NARR  2176
#define NW_OFF  0
#define NMS_OFF 32768
#define NMV_OFF(i) (NMS_OFF + NARR * (1 + (i)))
#define NNA_OFF (NMS_OFF + NARR * 4)            // 41472, [16][68]
#define NODE_SMEM_FLOATS (NNA_OFF + 16 * NROW)  // 42560
#define NODE_SMEM_BYTES  (NODE_SMEM_FLOATS * 4)

__global__ void __launch_bounds__(544, 1)
node_kernel(const float* __restrict__ node_attrs,
            float* __restrict__ out,
            int N)
{
    extern __shared__ float s[];
    const int tid  = threadIdx.x;
    const int lane = tid & 31;
    const int eo   = tid >> 5;      // 0..16
    const int eb   = eo << 2;       // 0..64

    for (int i = tid; i < 8192; i += 544)
        ((float4*)s)[i] = ((const float4*)g_WS)[i];

    const int ntiles = (N + QTILE - 1) / QTILE;

    for (int t = blockIdx.x; t < ntiles; t += gridDim.x) {
        const int n0 = t * QTILE;
        __syncthreads();

        // stage M (new layout: [n][ln][4] = ms,mv0,mv1,mv2)
        for (int q = tid; q < QTILE * 128; q += 544) {
            int e = q >> 7, f = q & 127;
            int n = n0 + e;
            float v = (n < N) ? g_M[(size_t)n * 128 + f] : 0.f;
            int ln = f >> 2, c = f & 3;
            if (c == 0) s[NMS_OFF + ln * NROW + e] = v;
            else        s[NMV_OFF(c - 1) + ln * NROW + e] = v;
        }
        // stage node_attrs
        for (int q = tid; q < QTILE * 16; q += 544) {
            int e = q >> 4, v = q & 15;
            int n = n0 + e;
            s[NNA_OFF + v * NROW + e] = (n < N) ? node_attrs[(size_t)n * 16 + v] : 0.f;
        }
        __syncthreads();

        u64 tot[8];
#pragma unroll
        for (int q = 0; q < 8; q++) tot[q] = 0ull;

#pragma unroll 1
        for (int v = 0; v < 16; v++) {
            u64 part[8];
#pragma unroll
            for (int q = 0; q < 8; q++) part[q] = 0ull;

            const int wbase = v * 64 + lane * 2;
#pragma unroll 4
            for (int u = 0; u < 32; u++) {
                float2 wv = *(const float2*)&s[NW_OFF + wbase + u * 1024];
                u64 w0 = splat2(wv.x), w1 = splat2(wv.y);
                int ao = u * NROW + eb;
                ulonglong2 m0 = *(const ulonglong2*)&s[NMS_OFF    + ao];
                ulonglong2 m1 = *(const ulonglong2*)&s[NMV_OFF(0) + ao];
                ulonglong2 m2 = *(const ulonglong2*)&s[NMV_OFF(1) + ao];
                ulonglong2 m3 = *(const ulonglong2*)&s[NMV_OFF(2) + ao];

                part[0] = fma2(m0.x, w0, part[0]); part[1] = fma2(m0.y, w0, part[1]);
                part[2] = fma2(m1.x, w1, part[2]); part[3] = fma2(m1.y, w1, part[3]);
                part[4] = fma2(m2.x, w1, part[4]); part[5] = fma2(m2.y, w1, part[5]);
                part[6] = fma2(m3.x, w1, part[6]); part[7] = fma2(m3.y, w1, part[7]);
            }

            u64 na0 = *(const u64*)&s[NNA_OFF + v * NROW + eb];
            u64 na1 = *(const u64*)&s[NNA_OFF + v * NROW + eb + 2];
#pragma unroll
            for (int q = 0; q < 8; q += 2) {
                tot[q]     = fma2(na0, part[q],     tot[q]);
                tot[q + 1] = fma2(na1, part[q + 1], tot[q + 1]);
            }
        }

        // epilogue: out = M + skip (output layout unchanged: ms[0:32], mv u*3+i)
#pragma unroll
        for (int p = 0; p < 2; p++) {
            float2 S  = unpk(tot[0 + p]);
            float2 V0 = unpk(tot[2 + p]);
            float2 V1 = unpk(tot[4 + p]);
            float2 V2 = unpk(tot[6 + p]);
#pragma unroll
            for (int h = 0; h < 2; h++) {
                int e = eb + 2 * p + h;
                int n = n0 + e;
                if (n >= N) continue;
                float* o = out + (size_t)n * 128;
                o[lane]              = s[NMS_OFF    + lane * NROW + e] + (h ? S.y  : S.x);
                o[32 + lane * 3 + 0] = s[NMV_OFF(0) + lane * NROW + e] + (h ? V0.y : V0.x);
                o[32 + lane * 3 + 1] = s[NMV_OFF(1) + lane * NROW + e] + (h ? V1.y : V1.x);
                o[32 + lane * 3 + 2] = s[NMV_OFF(2) + lane * NROW + e] + (h ? V2.y : V2.x);
            }
        }
    }
}

// ===========================================================================
// Launch
// ===========================================================================
extern "C" void kernel_launch(void* const* d_in, const int* in_sizes, int n_in,
                              void* d_out, int out_size)
{
    const float* node_attrs = (const float*)d_in[0];
    const float* node_feats = (const float*)d_in[1];
    const float* edge_attrs = (const float*)d_in[2];
    const float* edge_feats = (const float*)d_in[3];
    const int*   edge_index = (const int*)  d_in[4];
    const float* Wgen       = (const float*)d_in[5];
    const float* L1s        = (const float*)d_in[6];
    const float* L1v        = (const float*)d_in[7];
    const float* WS0        = (const float*)d_in[8];
    const float* WS1        = (const float*)d_in[9];
    const float* L2s        = (const float*)d_in[10];
    const float* L2v        = (const float*)d_in[11];
    float* out = (float*)d_out;

    const int N = in_sizes[0] / ATTRC;        // 10000
    const int E = in_sizes[3] / RADIALC;      // 100000
    const int ntiles = (N + QTILE - 1) / QTILE;   // 148

    cudaFuncSetAttribute(q_kernel,    cudaFuncAttributeMaxDynamicSharedMemorySize, Q_SMEM_BYTES);
    cudaFuncSetAttribute(node_kernel, cudaFuncAttributeMaxDynamicSharedMemorySize, NODE_SMEM_BYTES);

    prep_kernel<<<(N * 128 + 511) / 512, 512>>>(Wgen, L1s, L1v, WS0, WS1, L2s, L2v,
                                                N * 128, N);
    hist_kernel<<<(E + 511) / 512, 512>>>(edge_index, E);
    scan_kernel<<<1, 1024>>>(N);
    scatter_kernel<<<(E + 511) / 512, 512>>>(edge_index, E);
    q_kernel<<<ntiles, 544, Q_SMEM_BYTES>>>(node_feats, N);
    edge_kernel<<<148, 512>>>(edge_attrs, edge_feats, edge_index, E, N);
    node_kernel<<<ntiles, 544, NODE_SMEM_BYTES>>>(node_attrs, out, N);
}

// round 11
// speedup vs baseline: 3.3591x; 1.0600x over previous
#include <cuda_runtime.h>
#include <cuda_bf16.h>

typedef unsigned long long u64;

#define ATTRC    16
#define RADIALC  8
#define NMAX     10000
#define EMAX     100000

// ---------------------------------------------------------------------------
// Packed f32x2 helpers
// ---------------------------------------------------------------------------
__device__ __forceinline__ u64 fma2(u64 a, u64 b, u64 c) {
    u64 d; asm("fma.rn.f32x2 %0, %1, %2, %3;" : "=l"(d) : "l"(a), "l"(b), "l"(c)); return d;
}
__device__ __forceinline__ u64 splat2(float w) {
    u64 d; unsigned int b = __float_as_uint(w);
    asm("mov.b64 %0, {%1, %1};" : "=l"(d) : "r"(b)); return d;
}
__device__ __forceinline__ float2 unpk(u64 v) {
    unsigned int lo, hi; asm("mov.b64 {%0, %1}, %2;" : "=r"(lo), "=r"(hi) : "l"(v));
    return make_float2(__uint_as_float(lo), __uint_as_float(hi));
}
__device__ __forceinline__ void red_v4(float* p, float a, float b, float c, float d) {
    asm volatile("red.global.add.v4.f32 [%0], {%1, %2, %3, %4};"
                 :: "l"(p), "f"(a), "f"(b), "f"(c), "f"(d) : "memory");
}

// ---------------------------------------------------------------------------
// Device scratch
// ---------------------------------------------------------------------------
__device__ __align__(16) float g_WE[32768];          // [k=(r*32+u)][wp][4 blocks]
__device__ __align__(16) float g_WS[32768];          // [k2=(u*16+v)][wp][2 paths]
__device__ __align__(16) float g_M[NMAX * 128];      // messages [n][lane][4]=(ms,mv0,mv1,mv2)
__device__ __align__(16) float g_Q[NMAX * 2048];     // Q[n][g][r][w]
__device__ int g_cnt[NMAX];
__device__ int g_startArr[NMAX + 1];
__device__ int g_cur[NMAX];
__device__ int g_eidx[EMAX];
__device__ int g_work;                               // work-steal ticket

// ---------------------------------------------------------------------------
// Prep kernel: fold both weight sets + zero M + zero cnt, one launch.
//   c_edge = c_node = 1/128
// ---------------------------------------------------------------------------
__global__ void prep_kernel(const float* __restrict__ Wgen,
                            const float* __restrict__ L1s,
                            const float* __restrict__ L1v,
                            const float* __restrict__ WS0,
                            const float* __restrict__ WS1,
                            const float* __restrict__ L2s,
                            const float* __restrict__ L2v,
                            int nM, int N)
{
    int i = blockIdx.x * blockDim.x + threadIdx.x;
    if (i < nM) g_M[i] = 0.f;
    if (i < N)  g_cnt[i] = 0;

    if (i < 32768) {
        {   // fold edge weights
            int b   = i >> 13;
            int rem = i & 8191;
            int r   = rem >> 10;
            int u   = (rem >> 5) & 31;
            int wp  = rem & 31;
            const float* wg = Wgen + r * 4096 + b * 1024 + u * 32;
            const float* L  = (b == 1 || b == 2) ? L1v : L1s;
            float acc = 0.f;
#pragma unroll
            for (int w = 0; w < 32; w++) acc = fmaf(wg[w], L[w * 32 + wp], acc);
            float c = 0.0078125f;
            if (b == 3) c *= 0.57735026918962576f;   // fold 1/sqrt(3) into WD
            g_WE[(r * 32 + u) * 128 + wp * 4 + b] = acc * c;
        }
        {   // fold node weights
            int sb  = i >> 14;
            int rem = i & 16383;
            int uv  = rem >> 5;
            int wp  = rem & 31;
            const float* ws = (sb ? WS1 : WS0) + uv * 32;
            const float* L  = sb ? L2v : L2s;
            float acc = 0.f;
#pragma unroll
            for (int w = 0; w < 32; w++) acc = fmaf(ws[w], L[w * 32 + wp], acc);
            g_WS[uv * 64 + wp * 2 + sb] = acc * 0.0078125f;
        }
    }
}

// ---------------------------------------------------------------------------
// CSR: histogram
// ---------------------------------------------------------------------------
__global__ void hist_kernel(const int* __restrict__ edge_index, int E)
{
    int e = blockIdx.x * blockDim.x + threadIdx.x;
    if (e < E) atomicAdd(&g_cnt[edge_index[e]], 1);
}

// ---------------------------------------------------------------------------
// CSR: shfl-based exclusive scan (single block, 1024 threads, 4 barriers/batch)
// Also resets the edge work-steal counter.
// ---------------------------------------------------------------------------
__global__ void scan_kernel(int N)
{
    __shared__ int wsum[32];
    __shared__ int wbase[32];
    __shared__ int carry;
    const int tid  = threadIdx.x;
    const int lane = tid & 31;
    const int wid  = tid >> 5;

    if (tid == 0) { carry = 0; g_work = 0; }
    __syncthreads();

    for (int base = 0; base < N; base += 1024) {
        int i = base + tid;
        int v = (i < N) ? g_cnt[i] : 0;
        int x = v;
#pragma unroll
        for (int off = 1; off < 32; off <<= 1) {
            int t = __shfl_up_sync(0xffffffffu, x, off);
            if (lane >= off) x += t;
        }
        if (lane == 31) wsum[wid] = x;
        __syncthreads();

        if (wid == 0) {
            int sv = wsum[lane];
            int y  = sv;
#pragma unroll
            for (int off = 1; off < 32; off <<= 1) {
                int t = __shfl_up_sync(0xffffffffu, y, off);
                if (lane >= off) y += t;
            }
            wbase[lane] = y - sv;           // exclusive base per warp
            if (lane == 31) wsum[0] = y;    // batch total
        }
        __syncthreads();

        int c  = carry;
        int st = c + wbase[wid] + (x - v);  // exclusive position
        if (i < N) { g_startArr[i] = st; g_cur[i] = st; }
        __syncthreads();
        if (tid == 0) carry = c + wsum[0];
        __syncthreads();
    }
    if (tid == 0) g_startArr[N] = carry;
}

// ===========================================================================
// Q kernel: Q[n][g][r][w] = sum_u Wg[r][u][w] * x[n][u]
// Prologue also performs the CSR scatter (depends only on scan; overlaps the
// weight staging).  544 threads, 68-node tiles -> 148 tiles = 1 wave.
// ===========================================================================
#define QTILE 68
#define QROW  68
#define QARR  2176
#define QW_OFF 0
#define QX_OFF 32768
#define Q_SMEM_FLOATS (QX_OFF + 4 * QARR)
#define Q_SMEM_BYTES  (Q_SMEM_FLOATS * 4)

__global__ void __launch_bounds__(544, 1)
q_kernel(const float* __restrict__ node_feats,
         const int* __restrict__ edge_index,
         int N, int E)
{
    extern __shared__ float s[];
    const int tid  = threadIdx.x;
    const int lane = tid & 31;
    const int eo   = tid >> 5;
    const int eb   = eo << 2;

    // ---- CSR scatter (overlapped with weight staging below) ----
    for (int i = blockIdx.x * 544 + tid; i < E; i += gridDim.x * 544) {
        int pos = atomicAdd(&g_cur[edge_index[i]], 1);
        g_eidx[pos] = i;
    }

    for (int i = tid; i < 8192; i += 544)
        ((float4*)s)[i] = ((const float4*)g_WE)[i];

    const int ntiles = (N + QTILE - 1) / QTILE;

    for (int t = blockIdx.x; t < ntiles; t += gridDim.x) {
        const int n0 = t * QTILE;
        __syncthreads();

        for (int q = tid; q < QTILE * 128; q += 544) {
            int e = q >> 7, f = q & 127;
            int n = n0 + e;
            float v = (n < N) ? node_feats[(size_t)n * 128 + f] : 0.f;
            if (f < 32) {
                s[QX_OFF + f * QROW + e] = v;
            } else {
                int tt = f - 32;
                int uu = tt / 3;
                int ii = tt - uu * 3;
                s[QX_OFF + (1 + ii) * QARR + uu * QROW + e] = v;
            }
        }
        __syncthreads();

#pragma unroll 1
        for (int r = 0; r < 8; r++) {
            u64 acc[8][2];
#pragma unroll
            for (int g = 0; g < 8; g++) { acc[g][0] = 0ull; acc[g][1] = 0ull; }

            const int wbase2 = (r << 5) * 128 + lane * 4;
#pragma unroll 4
            for (int u = 0; u < 32; u++) {
                float4 wv = *(const float4*)&s[QW_OFF + wbase2 + u * 128];
                u64 wa = splat2(wv.x), wb = splat2(wv.y),
                    wc = splat2(wv.z), wd = splat2(wv.w);
                int xo = u * QROW + eb;
                ulonglong2 xs = *(const ulonglong2*)&s[QX_OFF + 0 * QARR + xo];
                ulonglong2 x0 = *(const ulonglong2*)&s[QX_OFF + 1 * QARR + xo];
                ulonglong2 x1 = *(const ulonglong2*)&s[QX_OFF + 2 * QARR + xo];
                ulonglong2 x2 = *(const ulonglong2*)&s[QX_OFF + 3 * QARR + xo];

                acc[0][0] = fma2(xs.x, wa, acc[0][0]); acc[0][1] = fma2(xs.y, wa, acc[0][1]);
                acc[1][0] = fma2(xs.x, wb, acc[1][0]); acc[1][1] = fma2(xs.y, wb, acc[1][1]);
                acc[2][0] = fma2(x0.x, wc, acc[2][0]); acc[2][1] = fma2(x0.y, wc, acc[2][1]);
                acc[3][0] = fma2(x1.x, wc, acc[3][0]); acc[3][1] = fma2(x1.y, wc, acc[3][1]);
                acc[4][0] = fma2(x2.x, wc, acc[4][0]); acc[4][1] = fma2(x2.y, wc, acc[4][1]);
                acc[5][0] = fma2(x0.x, wd, acc[5][0]); acc[5][1] = fma2(x0.y, wd, acc[5][1]);
                acc[6][0] = fma2(x1.x, wd, acc[6][0]); acc[6][1] = fma2(x1.y, wd, acc[6][1]);
                acc[7][0] = fma2(x2.x, wd, acc[7][0]); acc[7][1] = fma2(x2.y, wd, acc[7][1]);
            }

#pragma unroll
            for (int p = 0; p < 2; p++) {
#pragma unroll
                for (int h = 0; h < 2; h++) {
                    int n = n0 + eb + p * 2 + h;
                    if (n >= N) continue;
                    float* qn = g_Q + (size_t)n * 2048 + r * 32 + lane;
#pragma unroll
                    for (int g = 0; g < 8; g++) {
                        float2 f2 = unpk(acc[g][p]);
                        qn[g * 256] = h ? f2.y : f2.x;
                    }
                }
            }
        }
    }
}

// ===========================================================================
// Edge kernel (CSR, work-stealing): warp grabs a sender ticket; Q row in
// registers; v4 red scatter.
// ===========================================================================
__global__ void __launch_bounds__(512, 1)
edge_kernel(const float* __restrict__ edge_attrs,
            const float* __restrict__ edge_feats,
            const int*   __restrict__ edge_index,
            int E, int N)
{
    const int lane = threadIdx.x & 31;

    while (true) {
        int n = 0;
        if (lane == 0) n = atomicAdd(&g_work, 1);
        n = __shfl_sync(0xffffffffu, n, 0);
        if (n >= N) break;

        int s0 = g_startArr[n];
        int s1 = g_startArr[n + 1];
        if (s0 == s1) continue;

        const float* Qn = g_Q + (size_t)n * 2048 + lane;
        float q[8][8];
#pragma unroll
        for (int g = 0; g < 8; g++)
#pragma unroll
            for (int r = 0; r < 8; r++)
                q[g][r] = Qn[g * 256 + r * 32];

        for (int idx = s0; idx < s1; idx++) {
            int e = __ldg(&g_eidx[idx]);
            int rcv = __ldg(&edge_index[E + e]);
            float4 ea  = *(const float4*)&edge_attrs[(size_t)e * 4];
            float4 ef0 = *(const float4*)&edge_feats[(size_t)e * 8];
            float4 ef1 = *(const float4*)&edge_feats[(size_t)e * 8 + 4];

            float p[8];
#pragma unroll
            for (int g = 0; g < 8; g++) {
                float a =        q[g][0] * ef0.x;
                a = fmaf(q[g][1], ef0.y, a);
                a = fmaf(q[g][2], ef0.z, a);
                a = fmaf(q[g][3], ef0.w, a);
                a = fmaf(q[g][4], ef1.x, a);
                a = fmaf(q[g][5], ef1.y, a);
                a = fmaf(q[g][6], ef1.z, a);
                a = fmaf(q[g][7], ef1.w, a);
                p[g] = a;
            }

            float ms  = fmaf(p[0], ea.x, fmaf(p[5], ea.y, fmaf(p[6], ea.z, p[7] * ea.w)));
            float mv0 = fmaf(p[1], ea.y, p[2] * ea.x);
            float mv1 = fmaf(p[1], ea.z, p[3] * ea.x);
            float mv2 = fmaf(p[1], ea.w, p[4] * ea.x);

            red_v4(g_M + (size_t)rcv * 128 + lane * 4, ms, mv0, mv1, mv2);
        }
    }
}

// ===========================================================================
// Node kernel: 544 threads, 68-node tiles (1 wave), part-register scheme.
// ===========================================================================
#define NROW  68
#define NARR  2176
#define NW_OFF  0
#define NMS_OFF 32768
#define NMV_OFF(i) (NMS_OFF + NARR * (1 + (i)))
#define NNA_OFF (NMS_OFF + NARR * 4)
#define NODE_SMEM_FLOATS (NNA_OFF + 16 * NROW)
#define NODE_SMEM_BYTES  (NODE_SMEM_FLOATS * 4)

__global__ void __launch_bounds__(544, 1)
node_kernel(const float* __restrict__ node_attrs,
            float* __restrict__ out,
            int N)
{
    extern __shared__ float s[];
    const int tid  = threadIdx.x;
    const int lane = tid & 31;
    const int eo   = tid >> 5;
    const int eb   = eo << 2;

    for (int i = tid; i < 8192; i += 544)
        ((float4*)s)[i] = ((const float4*)g_WS)[i];

    const int ntiles = (N + QTILE - 1) / QTILE;

    for (int t = blockIdx.x; t < ntiles; t += gridDim.x) {
        const int n0 = t * QTILE;
        __syncthreads();

        // stage M ([n][ln][4] = ms,mv0,mv1,mv2)
        for (int q = tid; q < QTILE * 128; q += 544) {
            int e = q >> 7, f = q & 127;
            int n = n0 + e;
            float v = (n < N) ? g_M[(size_t)n * 128 + f] : 0.f;
            int ln = f >> 2, c = f & 3;
            if (c == 0) s[NMS_OFF + ln * NROW + e] = v;
            else        s[NMV_OFF(c - 1) + ln * NROW + e] = v;
        }
        for (int q = tid; q < QTILE * 16; q += 544) {
            int e = q >> 4, v = q & 15;
            int n = n0 + e;
            s[NNA_OFF + v * NROW + e] = (n < N) ? node_attrs[(size_t)n * 16 + v] : 0.f;
        }
        __syncthreads();

        u64 tot[8];
#pragma unroll
        for (int q = 0; q < 8; q++) tot[q] = 0ull;

#pragma unroll 1
        for (int v = 0; v < 16; v++) {
            u64 part[8];
#pragma unroll
            for (int q = 0; q < 8; q++) part[q] = 0ull;

            const int wbase = v * 64 + lane * 2;
#pragma unroll 4
            for (int u = 0; u < 32; u++) {
                float2 wv = *(const float2*)&s[NW_OFF + wbase + u * 1024];
                u64 w0 = splat2(wv.x), w1 = splat2(wv.y);
                int ao = u * NROW + eb;
                ulonglong2 m0 = *(const ulonglong2*)&s[NMS_OFF    + ao];
                ulonglong2 m1 = *(const ulonglong2*)&s[NMV_OFF(0) + ao];
                ulonglong2 m2 = *(const ulonglong2*)&s[NMV_OFF(1) + ao];
                ulonglong2 m3 = *(const ulonglong2*)&s[NMV_OFF(2) + ao];

                part[0] = fma2(m0.x, w0, part[0]); part[1] = fma2(m0.y, w0, part[1]);
                part[2] = fma2(m1.x, w1, part[2]); part[3] = fma2(m1.y, w1, part[3]);
                part[4] = fma2(m2.x, w1, part[4]); part[5] = fma2(m2.y, w1, part[5]);
                part[6] = fma2(m3.x, w1, part[6]); part[7] = fma2(m3.y, w1, part[7]);
            }

            u64 na0 = *(const u64*)&s[NNA_OFF + v * NROW + eb];
            u64 na1 = *(const u64*)&s[NNA_OFF + v * NROW + eb + 2];
#pragma unroll
            for (int q = 0; q < 8; q += 2) {
                tot[q]     = fma2(na0, part[q],     tot[q]);
                tot[q + 1] = fma2(na1, part[q + 1], tot[q + 1]);
            }
        }

#pragma unroll
        for (int p = 0; p < 2; p++) {
            float2 S  = unpk(tot[0 + p]);
            float2 V0 = unpk(tot[2 + p]);
            float2 V1 = unpk(tot[4 + p]);
            float2 V2 = unpk(tot[6 + p]);
#pragma unroll
            for (int h = 0; h < 2; h++) {
                int e = eb + 2 * p + h;
                int n = n0 + e;
                if (n >= N) continue;
                float* o = out + (size_t)n * 128;
                o[lane]              = s[NMS_OFF    + lane * NROW + e] + (h ? S.y  : S.x);
                o[32 + lane * 3 + 0] = s[NMV_OFF(0) + lane * NROW + e] + (h ? V0.y : V0.x);
                o[32 + lane * 3 + 1] = s[NMV_OFF(1) + lane * NROW + e] + (h ? V1.y : V1.x);
                o[32 + lane * 3 + 2] = s[NMV_OFF(2) + lane * NROW + e] + (h ? V2.y : V2.x);
            }
        }
    }
}

// ===========================================================================
// Launch
// ===========================================================================
extern "C" void kernel_launch(void* const* d_in, const int* in_sizes, int n_in,
                              void* d_out, int out_size)
{
    const float* node_attrs = (const float*)d_in[0];
    const float* node_feats = (const float*)d_in[1];
    const float* edge_attrs = (const float*)d_in[2];
    const float* edge_feats = (const float*)d_in[3];
    const int*   edge_index = (const int*)  d_in[4];
    const float* Wgen       = (const float*)d_in[5];
    const float* L1s        = (const float*)d_in[6];
    const float* L1v        = (const float*)d_in[7];
    const float* WS0        = (const float*)d_in[8];
    const float* WS1        = (const float*)d_in[9];
    const float* L2s        = (const float*)d_in[10];
    const float* L2v        = (const float*)d_in[11];
    float* out = (float*)d_out;

    const int N = in_sizes[0] / ATTRC;        // 10000
    const int E = in_sizes[3] / RADIALC;      // 100000
    const int ntiles = (N + QTILE - 1) / QTILE;   // 148

    cudaFuncSetAttribute(q_kernel,    cudaFuncAttributeMaxDynamicSharedMemorySize, Q_SMEM_BYTES);
    cudaFuncSetAttribute(node_kernel, cudaFuncAttributeMaxDynamicSharedMemorySize, NODE_SMEM_BYTES);

    prep_kernel<<<(N * 128 + 511) / 512, 512>>>(Wgen, L1s, L1v, WS0, WS1, L2s, L2v,
                                                N * 128, N);
    hist_kernel<<<(E + 511) / 512, 512>>>(edge_index, E);
    scan_kernel<<<1, 1024>>>(N);
    q_kernel<<<ntiles, 544, Q_SMEM_BYTES>>>(node_feats, edge_index, N, E);
    edge_kernel<<<148, 512>>>(edge_attrs, edge_feats, edge_index, E, N);
    node_kernel<<<ntiles, 544, NODE_SMEM_BYTES>>>(node_attrs, out, N);
}

// round 12
// speedup vs baseline: 3.5037x; 1.0431x over previous
#include <cuda_runtime.h>
#include <cuda_bf16.h>

typedef unsigned long long u64;

#define ATTRC    16
#define RADIALC  8
#define NMAX     10000
#define EMAX     100000

// ---------------------------------------------------------------------------
// Packed f32x2 helpers
// ---------------------------------------------------------------------------
__device__ __forceinline__ u64 fma2(u64 a, u64 b, u64 c) {
    u64 d; asm("fma.rn.f32x2 %0, %1, %2, %3;" : "=l"(d) : "l"(a), "l"(b), "l"(c)); return d;
}
__device__ __forceinline__ u64 splat2(float w) {
    u64 d; unsigned int b = __float_as_uint(w);
    asm("mov.b64 %0, {%1, %1};" : "=l"(d) : "r"(b)); return d;
}
__device__ __forceinline__ float2 unpk(u64 v) {
    unsigned int lo, hi; asm("mov.b64 {%0, %1}, %2;" : "=r"(lo), "=r"(hi) : "l"(v));
    return make_float2(__uint_as_float(lo), __uint_as_float(hi));
}
__device__ __forceinline__ void red_v4(float* p, float a, float b, float c, float d) {
    asm volatile("red.global.add.v4.f32 [%0], {%1, %2, %3, %4};"
                 :: "l"(p), "f"(a), "f"(b), "f"(c), "f"(d) : "memory");
}

// ---------------------------------------------------------------------------
// Device scratch  (g_cnt relies on static zero-init; scan re-zeroes it after
// reading so every graph replay sees zeros again)
// ---------------------------------------------------------------------------
__device__ __align__(16) float g_WE[32768];          // [k=(r*32+u)][wp][4 blocks]
__device__ __align__(16) float g_WS[32768];          // [k2=(u*16+v)][wp][2 paths]
__device__ __align__(16) float g_M[NMAX * 128];      // messages [n][lane][4]=(ms,mv0,mv1,mv2)
__device__ __align__(16) float g_Q[NMAX * 2048];     // Q[n][g][r][w]
__device__ int g_cnt[NMAX];
__device__ int g_startArr[NMAX + 1];
__device__ int g_cur[NMAX];
__device__ int g_eidx[EMAX];
__device__ int g_work;                               // work-steal ticket

// ---------------------------------------------------------------------------
// Prep kernel: fold both weight sets + zero M + sender histogram, one launch.
//   c_edge = c_node = 1/128
// ---------------------------------------------------------------------------
__global__ void prep_kernel(const float* __restrict__ Wgen,
                            const float* __restrict__ L1s,
                            const float* __restrict__ L1v,
                            const float* __restrict__ WS0,
                            const float* __restrict__ WS1,
                            const float* __restrict__ L2s,
                            const float* __restrict__ L2v,
                            const int* __restrict__ edge_index,
                            int nM, int E)
{
    int i = blockIdx.x * blockDim.x + threadIdx.x;
    if (i < nM) g_M[i] = 0.f;
    if (i < E)  atomicAdd(&g_cnt[edge_index[i]], 1);   // g_cnt zeroed by scan

    if (i < 32768) {
        {   // fold edge weights
            int b   = i >> 13;
            int rem = i & 8191;
            int r   = rem >> 10;
            int u   = (rem >> 5) & 31;
            int wp  = rem & 31;
            const float* wg = Wgen + r * 4096 + b * 1024 + u * 32;
            const float* L  = (b == 1 || b == 2) ? L1v : L1s;
            float acc = 0.f;
#pragma unroll
            for (int w = 0; w < 32; w++) acc = fmaf(wg[w], L[w * 32 + wp], acc);
            float c = 0.0078125f;
            if (b == 3) c *= 0.57735026918962576f;   // fold 1/sqrt(3) into WD
            g_WE[(r * 32 + u) * 128 + wp * 4 + b] = acc * c;
        }
        {   // fold node weights
            int sb  = i >> 14;
            int rem = i & 16383;
            int uv  = rem >> 5;
            int wp  = rem & 31;
            const float* ws = (sb ? WS1 : WS0) + uv * 32;
            const float* L  = sb ? L2v : L2s;
            float acc = 0.f;
#pragma unroll
            for (int w = 0; w < 32; w++) acc = fmaf(ws[w], L[w * 32 + wp], acc);
            g_WS[uv * 64 + wp * 2 + sb] = acc * 0.0078125f;
        }
    }
}

// ---------------------------------------------------------------------------
// CSR: shfl-based exclusive scan; self-resets g_cnt and g_work.
// ---------------------------------------------------------------------------
__global__ void scan_kernel(int N)
{
    __shared__ int wsum[32];
    __shared__ int wbase[32];
    __shared__ int carry;
    const int tid  = threadIdx.x;
    const int lane = tid & 31;
    const int wid  = tid >> 5;

    if (tid == 0) { carry = 0; g_work = 0; }
    __syncthreads();

    for (int base = 0; base < N; base += 1024) {
        int i = base + tid;
        int v = 0;
        if (i < N) { v = g_cnt[i]; g_cnt[i] = 0; }   // read + reset for next replay
        int x = v;
#pragma unroll
        for (int off = 1; off < 32; off <<= 1) {
            int t = __shfl_up_sync(0xffffffffu, x, off);
            if (lane >= off) x += t;
        }
        if (lane == 31) wsum[wid] = x;
        __syncthreads();

        if (wid == 0) {
            int sv = wsum[lane];
            int y  = sv;
#pragma unroll
            for (int off = 1; off < 32; off <<= 1) {
                int t = __shfl_up_sync(0xffffffffu, y, off);
                if (lane >= off) y += t;
            }
            wbase[lane] = y - sv;
            if (lane == 31) wsum[0] = y;
        }
        __syncthreads();

        int c  = carry;
        int st = c + wbase[wid] + (x - v);
        if (i < N) { g_startArr[i] = st; g_cur[i] = st; }
        __syncthreads();
        if (tid == 0) carry = c + wsum[0];
        __syncthreads();
    }
    if (tid == 0) g_startArr[N] = carry;
}

// ===========================================================================
// Q kernel: Q[n][g][r][w] = sum_u Wg[r][u][w] * x[n][u]  (+ CSR scatter)
// 544 threads, 68-node tiles -> 148 tiles = 1 wave.
// ===========================================================================
#define QTILE 68
#define QROW  68
#define QARR  2176
#define QW_OFF 0
#define QX_OFF 32768
#define Q_SMEM_FLOATS (QX_OFF + 4 * QARR)
#define Q_SMEM_BYTES  (Q_SMEM_FLOATS * 4)

__global__ void __launch_bounds__(544, 1)
q_kernel(const float* __restrict__ node_feats,
         const int* __restrict__ edge_index,
         int N, int E)
{
    extern __shared__ float s[];
    const int tid  = threadIdx.x;
    const int lane = tid & 31;
    const int eo   = tid >> 5;
    const int eb   = eo << 2;

    // CSR scatter (overlaps weight staging)
    for (int i = blockIdx.x * 544 + tid; i < E; i += gridDim.x * 544) {
        int pos = atomicAdd(&g_cur[edge_index[i]], 1);
        g_eidx[pos] = i;
    }

    for (int i = tid; i < 8192; i += 544)
        ((float4*)s)[i] = ((const float4*)g_WE)[i];

    const int ntiles = (N + QTILE - 1) / QTILE;

    for (int t = blockIdx.x; t < ntiles; t += gridDim.x) {
        const int n0 = t * QTILE;
        __syncthreads();

        for (int q = tid; q < QTILE * 128; q += 544) {
            int e = q >> 7, f = q & 127;
            int n = n0 + e;
            float v = (n < N) ? node_feats[(size_t)n * 128 + f] : 0.f;
            if (f < 32) {
                s[QX_OFF + f * QROW + e] = v;
            } else {
                int tt = f - 32;
                int uu = tt / 3;
                int ii = tt - uu * 3;
                s[QX_OFF + (1 + ii) * QARR + uu * QROW + e] = v;
            }
        }
        __syncthreads();

#pragma unroll 1
        for (int r = 0; r < 8; r++) {
            u64 acc[8][2];
#pragma unroll
            for (int g = 0; g < 8; g++) { acc[g][0] = 0ull; acc[g][1] = 0ull; }

            const int wbase2 = (r << 5) * 128 + lane * 4;
#pragma unroll 8
            for (int u = 0; u < 32; u++) {
                float4 wv = *(const float4*)&s[QW_OFF + wbase2 + u * 128];
                u64 wa = splat2(wv.x), wb = splat2(wv.y),
                    wc = splat2(wv.z), wd = splat2(wv.w);
                int xo = u * QROW + eb;
                ulonglong2 xs = *(const ulonglong2*)&s[QX_OFF + 0 * QARR + xo];
                ulonglong2 x0 = *(const ulonglong2*)&s[QX_OFF + 1 * QARR + xo];
                ulonglong2 x1 = *(const ulonglong2*)&s[QX_OFF + 2 * QARR + xo];
                ulonglong2 x2 = *(const ulonglong2*)&s[QX_OFF + 3 * QARR + xo];

                acc[0][0] = fma2(xs.x, wa, acc[0][0]); acc[0][1] = fma2(xs.y, wa, acc[0][1]);
                acc[1][0] = fma2(xs.x, wb, acc[1][0]); acc[1][1] = fma2(xs.y, wb, acc[1][1]);
                acc[2][0] = fma2(x0.x, wc, acc[2][0]); acc[2][1] = fma2(x0.y, wc, acc[2][1]);
                acc[3][0] = fma2(x1.x, wc, acc[3][0]); acc[3][1] = fma2(x1.y, wc, acc[3][1]);
                acc[4][0] = fma2(x2.x, wc, acc[4][0]); acc[4][1] = fma2(x2.y, wc, acc[4][1]);
                acc[5][0] = fma2(x0.x, wd, acc[5][0]); acc[5][1] = fma2(x0.y, wd, acc[5][1]);
                acc[6][0] = fma2(x1.x, wd, acc[6][0]); acc[6][1] = fma2(x1.y, wd, acc[6][1]);
                acc[7][0] = fma2(x2.x, wd, acc[7][0]); acc[7][1] = fma2(x2.y, wd, acc[7][1]);
            }

#pragma unroll
            for (int p = 0; p < 2; p++) {
#pragma unroll
                for (int h = 0; h < 2; h++) {
                    int n = n0 + eb + p * 2 + h;
                    if (n >= N) continue;
                    float* qn = g_Q + (size_t)n * 2048 + r * 32 + lane;
#pragma unroll
                    for (int g = 0; g < 8; g++) {
                        float2 f2 = unpk(acc[g][p]);
                        qn[g * 256] = h ? f2.y : f2.x;
                    }
                }
            }
        }
    }
}

// ===========================================================================
// Edge kernel (CSR, work-stealing): warp grabs a sender ticket; Q row in
// registers; v4 red scatter.
// ===========================================================================
__global__ void __launch_bounds__(512, 1)
edge_kernel(const float* __restrict__ edge_attrs,
            const float* __restrict__ edge_feats,
            const int*   __restrict__ edge_index,
            int E, int N)
{
    const int lane = threadIdx.x & 31;

    while (true) {
        int n = 0;
        if (lane == 0) n = atomicAdd(&g_work, 1);
        n = __shfl_sync(0xffffffffu, n, 0);
        if (n >= N) break;

        int s0 = g_startArr[n];
        int s1 = g_startArr[n + 1];
        if (s0 == s1) continue;

        const float* Qn = g_Q + (size_t)n * 2048 + lane;
        float q[8][8];
#pragma unroll
        for (int g = 0; g < 8; g++)
#pragma unroll
            for (int r = 0; r < 8; r++)
                q[g][r] = Qn[g * 256 + r * 32];

        for (int idx = s0; idx < s1; idx++) {
            int e = __ldg(&g_eidx[idx]);
            int rcv = __ldg(&edge_index[E + e]);
            float4 ea  = *(const float4*)&edge_attrs[(size_t)e * 4];
            float4 ef0 = *(const float4*)&edge_feats[(size_t)e * 8];
            float4 ef1 = *(const float4*)&edge_feats[(size_t)e * 8 + 4];

            float p[8];
#pragma unroll
            for (int g = 0; g < 8; g++) {
                float a =        q[g][0] * ef0.x;
                a = fmaf(q[g][1], ef0.y, a);
                a = fmaf(q[g][2], ef0.z, a);
                a = fmaf(q[g][3], ef0.w, a);
                a = fmaf(q[g][4], ef1.x, a);
                a = fmaf(q[g][5], ef1.y, a);
                a = fmaf(q[g][6], ef1.z, a);
                a = fmaf(q[g][7], ef1.w, a);
                p[g] = a;
            }

            float ms  = fmaf(p[0], ea.x, fmaf(p[5], ea.y, fmaf(p[6], ea.z, p[7] * ea.w)));
            float mv0 = fmaf(p[1], ea.y, p[2] * ea.x);
            float mv1 = fmaf(p[1], ea.z, p[3] * ea.x);
            float mv2 = fmaf(p[1], ea.w, p[4] * ea.x);

            red_v4(g_M + (size_t)rcv * 128 + lane * 4, ms, mv0, mv1, mv2);
        }
    }
}

// ===========================================================================
// Node kernel: 544 threads, 68-node tiles, u-chunk(4) register caching of M.
//   out[w,e] = M[w,e] + sum_uc sum_v na[v,e] * (sum_{u in uc} WS[u,v,w] M[u,e])
// ===========================================================================
#define NROW  68
#define NARR  2176
#define NW_OFF  0
#define NMS_OFF 32768
#define NMV_OFF(i) (NMS_OFF + NARR * (1 + (i)))
#define NNA_OFF (NMS_OFF + NARR * 4)
#define NODE_SMEM_FLOATS (NNA_OFF + 16 * NROW)
#define NODE_SMEM_BYTES  (NODE_SMEM_FLOATS * 4)

__global__ void __launch_bounds__(544, 1)
node_kernel(const float* __restrict__ node_attrs,
            float* __restrict__ out,
            int N)
{
    extern __shared__ float s[];
    const int tid  = threadIdx.x;
    const int lane = tid & 31;
    const int eo   = tid >> 5;
    const int eb   = eo << 2;

    for (int i = tid; i < 8192; i += 544)
        ((float4*)s)[i] = ((const float4*)g_WS)[i];

    const int ntiles = (N + QTILE - 1) / QTILE;

    for (int t = blockIdx.x; t < ntiles; t += gridDim.x) {
        const int n0 = t * QTILE;
        __syncthreads();

        // stage M ([n][ln][4] = ms,mv0,mv1,mv2)
        for (int q = tid; q < QTILE * 128; q += 544) {
            int e = q >> 7, f = q & 127;
            int n = n0 + e;
            float v = (n < N) ? g_M[(size_t)n * 128 + f] : 0.f;
            int ln = f >> 2, c = f & 3;
            if (c == 0) s[NMS_OFF + ln * NROW + e] = v;
            else        s[NMV_OFF(c - 1) + ln * NROW + e] = v;
        }
        for (int q = tid; q < QTILE * 16; q += 544) {
            int e = q >> 4, v = q & 15;
            int n = n0 + e;
            s[NNA_OFF + v * NROW + e] = (n < N) ? node_attrs[(size_t)n * 16 + v] : 0.f;
        }
        __syncthreads();

        u64 tot[8];
#pragma unroll
        for (int q = 0; q < 8; q++) tot[q] = 0ull;

#pragma unroll 1
        for (int uc = 0; uc < 32; uc += 4) {
            // cache M for 4 u-values across the whole v loop (64 regs)
            ulonglong2 mm[4][4];
#pragma unroll
            for (int j = 0; j < 4; j++) {
                int ao = (uc + j) * NROW + eb;
                mm[j][0] = *(const ulonglong2*)&s[NMS_OFF    + ao];
                mm[j][1] = *(const ulonglong2*)&s[NMV_OFF(0) + ao];
                mm[j][2] = *(const ulonglong2*)&s[NMV_OFF(1) + ao];
                mm[j][3] = *(const ulonglong2*)&s[NMV_OFF(2) + ao];
            }

#pragma unroll 1
            for (int v = 0; v < 16; v++) {
                u64 part[8];
#pragma unroll
                for (int q = 0; q < 8; q++) part[q] = 0ull;

#pragma unroll
                for (int j = 0; j < 4; j++) {
                    float2 wv = *(const float2*)&s[NW_OFF + ((uc + j) * 16 + v) * 64 + lane * 2];
                    u64 w0 = splat2(wv.x), w1 = splat2(wv.y);
                    part[0] = fma2(mm[j][0].x, w0, part[0]); part[1] = fma2(mm[j][0].y, w0, part[1]);
                    part[2] = fma2(mm[j][1].x, w1, part[2]); part[3] = fma2(mm[j][1].y, w1, part[3]);
                    part[4] = fma2(mm[j][2].x, w1, part[4]); part[5] = fma2(mm[j][2].y, w1, part[5]);
                    part[6] = fma2(mm[j][3].x, w1, part[6]); part[7] = fma2(mm[j][3].y, w1, part[7]);
                }

                ulonglong2 na = *(const ulonglong2*)&s[NNA_OFF + v * NROW + eb];
#pragma unroll
                for (int q = 0; q < 8; q += 2) {
                    tot[q]     = fma2(na.x, part[q],     tot[q]);
                    tot[q + 1] = fma2(na.y, part[q + 1], tot[q + 1]);
                }
            }
        }

#pragma unroll
        for (int p = 0; p < 2; p++) {
            float2 S  = unpk(tot[0 + p]);
            float2 V0 = unpk(tot[2 + p]);
            float2 V1 = unpk(tot[4 + p]);
            float2 V2 = unpk(tot[6 + p]);
#pragma unroll
            for (int h = 0; h < 2; h++) {
                int e = eb + 2 * p + h;
                int n = n0 + e;
                if (n >= N) continue;
                float* o = out + (size_t)n * 128;
                o[lane]              = s[NMS_OFF    + lane * NROW + e] + (h ? S.y  : S.x);
                o[32 + lane * 3 + 0] = s[NMV_OFF(0) + lane * NROW + e] + (h ? V0.y : V0.x);
                o[32 + lane * 3 + 1] = s[NMV_OFF(1) + lane * NROW + e] + (h ? V1.y : V1.x);
                o[32 + lane * 3 + 2] = s[NMV_OFF(2) + lane * NROW + e] + (h ? V2.y : V2.x);
            }
        }
    }
}

// ===========================================================================
// Launch
// ===========================================================================
extern "C" void kernel_launch(void* const* d_in, const int* in_sizes, int n_in,
                              void* d_out, int out_size)
{
    const float* node_attrs = (const float*)d_in[0];
    const float* node_feats = (const float*)d_in[1];
    const float* edge_attrs = (const float*)d_in[2];
    const float* edge_feats = (const float*)d_in[3];
    const int*   edge_index = (const int*)  d_in[4];
    const float* Wgen       = (const float*)d_in[5];
    const float* L1s        = (const float*)d_in[6];
    const float* L1v        = (const float*)d_in[7];
    const float* WS0        = (const float*)d_in[8];
    const float* WS1        = (const float*)d_in[9];
    const float* L2s        = (const float*)d_in[10];
    const float* L2v        = (const float*)d_in[11];
    float* out = (float*)d_out;

    const int N = in_sizes[0] / ATTRC;        // 10000
    const int E = in_sizes[3] / RADIALC;      // 100000
    const int ntiles = (N + QTILE - 1) / QTILE;   // 148

    cudaFuncSetAttribute(q_kernel,    cudaFuncAttributeMaxDynamicSharedMemorySize, Q_SMEM_BYTES);
    cudaFuncSetAttribute(node_kernel, cudaFuncAttributeMaxDynamicSharedMemorySize, NODE_SMEM_BYTES);

    prep_kernel<<<(N * 128 + 511) / 512, 512>>>(Wgen, L1s, L1v, WS0, WS1, L2s, L2v,
                                                edge_index, N * 128, E);
    scan_kernel<<<1, 1024>>>(N);
    q_kernel<<<ntiles, 544, Q_SMEM_BYTES>>>(node_feats, edge_index, N, E);
    edge_kernel<<<148, 512>>>(edge_attrs, edge_feats, edge_index, E, N);
    node_kernel<<<ntiles, 544, NODE_SMEM_BYTES>>>(node_attrs, out, N);
}

// round 13
// speedup vs baseline: 3.7419x; 1.0680x over previous
#include <cuda_runtime.h>
#include <cuda_fp16.h>

typedef unsigned long long u64;

#define ATTRC    16
#define RADIALC  8
#define NMAX     10000
#define EMAX     100000

// ---------------------------------------------------------------------------
// Packed f32x2 helpers
// ---------------------------------------------------------------------------
__device__ __forceinline__ u64 fma2(u64 a, u64 b, u64 c) {
    u64 d; asm("fma.rn.f32x2 %0, %1, %2, %3;" : "=l"(d) : "l"(a), "l"(b), "l"(c)); return d;
}
__device__ __forceinline__ u64 splat2(float w) {
    u64 d; unsigned int b = __float_as_uint(w);
    asm("mov.b64 %0, {%1, %1};" : "=l"(d) : "r"(b)); return d;
}
__device__ __forceinline__ float2 unpk(u64 v) {
    unsigned int lo, hi; asm("mov.b64 {%0, %1}, %2;" : "=r"(lo), "=r"(hi) : "l"(v));
    return make_float2(__uint_as_float(lo), __uint_as_float(hi));
}
__device__ __forceinline__ void red_v4(float* p, float a, float b, float c, float d) {
    asm volatile("red.global.add.v4.f32 [%0], {%1, %2, %3, %4};"
                 :: "l"(p), "f"(a), "f"(b), "f"(c), "f"(d) : "memory");
}

// ---------------------------------------------------------------------------
// Device scratch  (g_cnt relies on static zero-init; scan re-zeroes it after
// reading so every graph replay sees zeros again)
// ---------------------------------------------------------------------------
__device__ __align__(16) float  g_WE[32768];          // [k=(r*32+u)][wp][4 blocks]
__device__ __align__(16) float  g_WS[32768];          // [k2=(u*16+v)][wp][2 paths]
__device__ __align__(16) float  g_M[NMAX * 128];      // messages [n][lane][4]=(ms,mv0,mv1,mv2)
__device__ __align__(16) __half g_Q[NMAX * 2048];     // Q[n][g][r][w]  (fp16, 41 MB -> L2-resident)
__device__ int g_cnt[NMAX];
__device__ int g_startArr[NMAX + 1];
__device__ int g_cur[NMAX];
__device__ int g_eidx[EMAX];
__device__ int g_work;                                // work-steal ticket

// ---------------------------------------------------------------------------
// Prep kernel: fold both weight sets + zero M + sender histogram, one launch.
//   c_edge = c_node = 1/128
// ---------------------------------------------------------------------------
__global__ void prep_kernel(const float* __restrict__ Wgen,
                            const float* __restrict__ L1s,
                            const float* __restrict__ L1v,
                            const float* __restrict__ WS0,
                            const float* __restrict__ WS1,
                            const float* __restrict__ L2s,
                            const float* __restrict__ L2v,
                            const int* __restrict__ edge_index,
                            int nM, int E)
{
    int i = blockIdx.x * blockDim.x + threadIdx.x;
    if (i < nM) g_M[i] = 0.f;
    if (i < E)  atomicAdd(&g_cnt[edge_index[i]], 1);   // g_cnt zeroed by scan

    if (i < 32768) {
        {   // fold edge weights
            int b   = i >> 13;
            int rem = i & 8191;
            int r   = rem >> 10;
            int u   = (rem >> 5) & 31;
            int wp  = rem & 31;
            const float* wg = Wgen + r * 4096 + b * 1024 + u * 32;
            const float* L  = (b == 1 || b == 2) ? L1v : L1s;
            float acc = 0.f;
#pragma unroll
            for (int w = 0; w < 32; w++) acc = fmaf(wg[w], L[w * 32 + wp], acc);
            float c = 0.0078125f;
            if (b == 3) c *= 0.57735026918962576f;   // fold 1/sqrt(3) into WD
            g_WE[(r * 32 + u) * 128 + wp * 4 + b] = acc * c;
        }
        {   // fold node weights
            int sb  = i >> 14;
            int rem = i & 16383;
            int uv  = rem >> 5;
            int wp  = rem & 31;
            const float* ws = (sb ? WS1 : WS0) + uv * 32;
            const float* L  = sb ? L2v : L2s;
            float acc = 0.f;
#pragma unroll
            for (int w = 0; w < 32; w++) acc = fmaf(ws[w], L[w * 32 + wp], acc);
            g_WS[uv * 64 + wp * 2 + sb] = acc * 0.0078125f;
        }
    }
}

// ---------------------------------------------------------------------------
// CSR: shfl-based exclusive scan; self-resets g_cnt and g_work.
// ---------------------------------------------------------------------------
__global__ void scan_kernel(int N)
{
    __shared__ int wsum[32];
    __shared__ int wbase[32];
    __shared__ int carry;
    const int tid  = threadIdx.x;
    const int lane = tid & 31;
    const int wid  = tid >> 5;

    if (tid == 0) { carry = 0; g_work = 0; }
    __syncthreads();

    for (int base = 0; base < N; base += 1024) {
        int i = base + tid;
        int v = 0;
        if (i < N) { v = g_cnt[i]; g_cnt[i] = 0; }   // read + reset for next replay
        int x = v;
#pragma unroll
        for (int off = 1; off < 32; off <<= 1) {
            int t = __shfl_up_sync(0xffffffffu, x, off);
            if (lane >= off) x += t;
        }
        if (lane == 31) wsum[wid] = x;
        __syncthreads();

        if (wid == 0) {
            int sv = wsum[lane];
            int y  = sv;
#pragma unroll
            for (int off = 1; off < 32; off <<= 1) {
                int t = __shfl_up_sync(0xffffffffu, y, off);
                if (lane >= off) y += t;
            }
            wbase[lane] = y - sv;
            if (lane == 31) wsum[0] = y;
        }
        __syncthreads();

        int c  = carry;
        int st = c + wbase[wid] + (x - v);
        if (i < N) { g_startArr[i] = st; g_cur[i] = st; }
        __syncthreads();
        if (tid == 0) carry = c + wsum[0];
        __syncthreads();
    }
    if (tid == 0) g_startArr[N] = carry;
}

// ===========================================================================
// Q kernel: Q[n][g][r][w] = sum_u Wg[r][u][w] * x[n][u]  (+ CSR scatter)
// 544 threads, 68-node tiles -> 148 tiles = 1 wave.  Q stored fp16.
// ===========================================================================
#define QTILE 68
#define QROW  68
#define QARR  2176
#define QW_OFF 0
#define QX_OFF 32768
#define Q_SMEM_FLOATS (QX_OFF + 4 * QARR)
#define Q_SMEM_BYTES  (Q_SMEM_FLOATS * 4)

__global__ void __launch_bounds__(544, 1)
q_kernel(const float* __restrict__ node_feats,
         const int* __restrict__ edge_index,
         int N, int E)
{
    extern __shared__ float s[];
    const int tid  = threadIdx.x;
    const int lane = tid & 31;
    const int eo   = tid >> 5;
    const int eb   = eo << 2;

    // CSR scatter (overlaps weight staging)
    for (int i = blockIdx.x * 544 + tid; i < E; i += gridDim.x * 544) {
        int pos = atomicAdd(&g_cur[edge_index[i]], 1);
        g_eidx[pos] = i;
    }

    for (int i = tid; i < 8192; i += 544)
        ((float4*)s)[i] = ((const float4*)g_WE)[i];

    const int ntiles = (N + QTILE - 1) / QTILE;

    for (int t = blockIdx.x; t < ntiles; t += gridDim.x) {
        const int n0 = t * QTILE;
        __syncthreads();

        for (int q = tid; q < QTILE * 128; q += 544) {
            int e = q >> 7, f = q & 127;
            int n = n0 + e;
            float v = (n < N) ? node_feats[(size_t)n * 128 + f] : 0.f;
            if (f < 32) {
                s[QX_OFF + f * QROW + e] = v;
            } else {
                int tt = f - 32;
                int uu = tt / 3;
                int ii = tt - uu * 3;
                s[QX_OFF + (1 + ii) * QARR + uu * QROW + e] = v;
            }
        }
        __syncthreads();

#pragma unroll 1
        for (int r = 0; r < 8; r++) {
            u64 acc[8][2];
#pragma unroll
            for (int g = 0; g < 8; g++) { acc[g][0] = 0ull; acc[g][1] = 0ull; }

            const int wbase2 = (r << 5) * 128 + lane * 4;
#pragma unroll 8
            for (int u = 0; u < 32; u++) {
                float4 wv = *(const float4*)&s[QW_OFF + wbase2 + u * 128];
                u64 wa = splat2(wv.x), wb = splat2(wv.y),
                    wc = splat2(wv.z), wd = splat2(wv.w);
                int xo = u * QROW + eb;
                ulonglong2 xs = *(const ulonglong2*)&s[QX_OFF + 0 * QARR + xo];
                ulonglong2 x0 = *(const ulonglong2*)&s[QX_OFF + 1 * QARR + xo];
                ulonglong2 x1 = *(const ulonglong2*)&s[QX_OFF + 2 * QARR + xo];
                ulonglong2 x2 = *(const ulonglong2*)&s[QX_OFF + 3 * QARR + xo];

                acc[0][0] = fma2(xs.x, wa, acc[0][0]); acc[0][1] = fma2(xs.y, wa, acc[0][1]);
                acc[1][0] = fma2(xs.x, wb, acc[1][0]); acc[1][1] = fma2(xs.y, wb, acc[1][1]);
                acc[2][0] = fma2(x0.x, wc, acc[2][0]); acc[2][1] = fma2(x0.y, wc, acc[2][1]);
                acc[3][0] = fma2(x1.x, wc, acc[3][0]); acc[3][1] = fma2(x1.y, wc, acc[3][1]);
                acc[4][0] = fma2(x2.x, wc, acc[4][0]); acc[4][1] = fma2(x2.y, wc, acc[4][1]);
                acc[5][0] = fma2(x0.x, wd, acc[5][0]); acc[5][1] = fma2(x0.y, wd, acc[5][1]);
                acc[6][0] = fma2(x1.x, wd, acc[6][0]); acc[6][1] = fma2(x1.y, wd, acc[6][1]);
                acc[7][0] = fma2(x2.x, wd, acc[7][0]); acc[7][1] = fma2(x2.y, wd, acc[7][1]);
            }

#pragma unroll
            for (int p = 0; p < 2; p++) {
#pragma unroll
                for (int h = 0; h < 2; h++) {
                    int n = n0 + eb + p * 2 + h;
                    if (n >= N) continue;
                    __half* qn = g_Q + (size_t)n * 2048 + r * 32 + lane;
#pragma unroll
                    for (int g = 0; g < 8; g++) {
                        float2 f2 = unpk(acc[g][p]);
                        qn[g * 256] = __float2half_rn(h ? f2.y : f2.x);
                    }
                }
            }
        }
    }
}

// ===========================================================================
// Edge kernel (CSR, work-stealing): warp grabs a sender ticket; fp16 Q row
// converted into fp32 registers; v4 red scatter.
// ===========================================================================
__global__ void __launch_bounds__(512, 1)
edge_kernel(const float* __restrict__ edge_attrs,
            const float* __restrict__ edge_feats,
            const int*   __restrict__ edge_index,
            int E, int N)
{
    const int lane = threadIdx.x & 31;

    while (true) {
        int n = 0;
        if (lane == 0) n = atomicAdd(&g_work, 1);
        n = __shfl_sync(0xffffffffu, n, 0);
        if (n >= N) break;

        int s0 = g_startArr[n];
        int s1 = g_startArr[n + 1];
        if (s0 == s1) continue;

        const __half* Qn = g_Q + (size_t)n * 2048 + lane;
        float q[8][8];
#pragma unroll
        for (int g = 0; g < 8; g++)
#pragma unroll
            for (int r = 0; r < 8; r++)
                q[g][r] = __half2float(Qn[g * 256 + r * 32]);

        for (int idx = s0; idx < s1; idx++) {
            int e = __ldg(&g_eidx[idx]);
            int rcv = __ldg(&edge_index[E + e]);
            float4 ea  = *(const float4*)&edge_attrs[(size_t)e * 4];
            float4 ef0 = *(const float4*)&edge_feats[(size_t)e * 8];
            float4 ef1 = *(const float4*)&edge_feats[(size_t)e * 8 + 4];

            float p[8];
#pragma unroll
            for (int g = 0; g < 8; g++) {
                float a =        q[g][0] * ef0.x;
                a = fmaf(q[g][1], ef0.y, a);
                a = fmaf(q[g][2], ef0.z, a);
                a = fmaf(q[g][3], ef0.w, a);
                a = fmaf(q[g][4], ef1.x, a);
                a = fmaf(q[g][5], ef1.y, a);
                a = fmaf(q[g][6], ef1.z, a);
                a = fmaf(q[g][7], ef1.w, a);
                p[g] = a;
            }

            float ms  = fmaf(p[0], ea.x, fmaf(p[5], ea.y, fmaf(p[6], ea.z, p[7] * ea.w)));
            float mv0 = fmaf(p[1], ea.y, p[2] * ea.x);
            float mv1 = fmaf(p[1], ea.z, p[3] * ea.x);
            float mv2 = fmaf(p[1], ea.w, p[4] * ea.x);

            red_v4(g_M + (size_t)rcv * 128 + lane * 4, ms, mv0, mv1, mv2);
        }
    }
}

// ===========================================================================
// Node kernel: 544 threads, 68-node tiles, u-chunk(4) register caching of M.
// ===========================================================================
#define NROW  68
#define NARR  2176
#define NW_OFF  0
#define NMS_OFF 32768
#define NMV_OFF(i) (NMS_OFF + NARR * (1 + (i)))
#define NNA_OFF (NMS_OFF + NARR * 4)
#define NODE_SMEM_FLOATS (NNA_OFF + 16 * NROW)
#define NODE_SMEM_BYTES  (NODE_SMEM_FLOATS * 4)

__global__ void __launch_bounds__(544, 1)
node_kernel(const float* __restrict__ node_attrs,
            float* __restrict__ out,
            int N)
{
    extern __shared__ float s[];
    const int tid  = threadIdx.x;
    const int lane = tid & 31;
    const int eo   = tid >> 5;
    const int eb   = eo << 2;

    for (int i = tid; i < 8192; i += 544)
        ((float4*)s)[i] = ((const float4*)g_WS)[i];

    const int ntiles = (N + QTILE - 1) / QTILE;

    for (int t = blockIdx.x; t < ntiles; t += gridDim.x) {
        const int n0 = t * QTILE;
        __syncthreads();

        // stage M ([n][ln][4] = ms,mv0,mv1,mv2)
        for (int q = tid; q < QTILE * 128; q += 544) {
            int e = q >> 7, f = q & 127;
            int n = n0 + e;
            float v = (n < N) ? g_M[(size_t)n * 128 + f] : 0.f;
            int ln = f >> 2, c = f & 3;
            if (c == 0) s[NMS_OFF + ln * NROW + e] = v;
            else        s[NMV_OFF(c - 1) + ln * NROW + e] = v;
        }
        for (int q = tid; q < QTILE * 16; q += 544) {
            int e = q >> 4, v = q & 15;
            int n = n0 + e;
            s[NNA_OFF + v * NROW + e] = (n < N) ? node_attrs[(size_t)n * 16 + v] : 0.f;
        }
        __syncthreads();

        u64 tot[8];
#pragma unroll
        for (int q = 0; q < 8; q++) tot[q] = 0ull;

#pragma unroll 1
        for (int uc = 0; uc < 32; uc += 4) {
            ulonglong2 mm[4][4];
#pragma unroll
            for (int j = 0; j < 4; j++) {
                int ao = (uc + j) * NROW + eb;
                mm[j][0] = *(const ulonglong2*)&s[NMS_OFF    + ao];
                mm[j][1] = *(const ulonglong2*)&s[NMV_OFF(0) + ao];
                mm[j][2] = *(const ulonglong2*)&s[NMV_OFF(1) + ao];
                mm[j][3] = *(const ulonglong2*)&s[NMV_OFF(2) + ao];
            }

#pragma unroll 1
            for (int v = 0; v < 16; v++) {
                u64 part[8];
#pragma unroll
                for (int q = 0; q < 8; q++) part[q] = 0ull;

#pragma unroll
                for (int j = 0; j < 4; j++) {
                    float2 wv = *(const float2*)&s[NW_OFF + ((uc + j) * 16 + v) * 64 + lane * 2];
                    u64 w0 = splat2(wv.x), w1 = splat2(wv.y);
                    part[0] = fma2(mm[j][0].x, w0, part[0]); part[1] = fma2(mm[j][0].y, w0, part[1]);
                    part[2] = fma2(mm[j][1].x, w1, part[2]); part[3] = fma2(mm[j][1].y, w1, part[3]);
                    part[4] = fma2(mm[j][2].x, w1, part[4]); part[5] = fma2(mm[j][2].y, w1, part[5]);
                    part[6] = fma2(mm[j][3].x, w1, part[6]); part[7] = fma2(mm[j][3].y, w1, part[7]);
                }

                ulonglong2 na = *(const ulonglong2*)&s[NNA_OFF + v * NROW + eb];
#pragma unroll
                for (int q = 0; q < 8; q += 2) {
                    tot[q]     = fma2(na.x, part[q],     tot[q]);
                    tot[q + 1] = fma2(na.y, part[q + 1], tot[q + 1]);
                }
            }
        }

#pragma unroll
        for (int p = 0; p < 2; p++) {
            float2 S  = unpk(tot[0 + p]);
            float2 V0 = unpk(tot[2 + p]);
            float2 V1 = unpk(tot[4 + p]);
            float2 V2 = unpk(tot[6 + p]);
#pragma unroll
            for (int h = 0; h < 2; h++) {
                int e = eb + 2 * p + h;
                int n = n0 + e;
                if (n >= N) continue;
                float* o = out + (size_t)n * 128;
                o[lane]              = s[NMS_OFF    + lane * NROW + e] + (h ? S.y  : S.x);
                o[32 + lane * 3 + 0] = s[NMV_OFF(0) + lane * NROW + e] + (h ? V0.y : V0.x);
                o[32 + lane * 3 + 1] = s[NMV_OFF(1) + lane * NROW + e] + (h ? V1.y : V1.x);
                o[32 + lane * 3 + 2] = s[NMV_OFF(2) + lane * NROW + e] + (h ? V2.y : V2.x);
            }
        }
    }
}

// ===========================================================================
// Launch
// ===========================================================================
extern "C" void kernel_launch(void* const* d_in, const int* in_sizes, int n_in,
                              void* d_out, int out_size)
{
    const float* node_attrs = (const float*)d_in[0];
    const float* node_feats = (const float*)d_in[1];
    const float* edge_attrs = (const float*)d_in[2];
    const float* edge_feats = (const float*)d_in[3];
    const int*   edge_index = (const int*)  d_in[4];
    const float* Wgen       = (const float*)d_in[5];
    const float* L1s        = (const float*)d_in[6];
    const float* L1v        = (const float*)d_in[7];
    const float* WS0        = (const float*)d_in[8];
    const float* WS1        = (const float*)d_in[9];
    const float* L2s        = (const float*)d_in[10];
    const float* L2v        = (const float*)d_in[11];
    float* out = (float*)d_out;

    const int N = in_sizes[0] / ATTRC;        // 10000
    const int E = in_sizes[3] / RADIALC;      // 100000
    const int ntiles = (N + QTILE - 1) / QTILE;   // 148

    cudaFuncSetAttribute(q_kernel,    cudaFuncAttributeMaxDynamicSharedMemorySize, Q_SMEM_BYTES);
    cudaFuncSetAttribute(node_kernel, cudaFuncAttributeMaxDynamicSharedMemorySize, NODE_SMEM_BYTES);

    prep_kernel<<<(N * 128 + 511) / 512, 512>>>(Wgen, L1s, L1v, WS0, WS1, L2s, L2v,
                                                edge_index, N * 128, E);
    scan_kernel<<<1, 1024>>>(N);
    q_kernel<<<ntiles, 544, Q_SMEM_BYTES>>>(node_feats, edge_index, N, E);
    edge_kernel<<<148, 512>>>(edge_attrs, edge_feats, edge_index, E, N);
    node_kernel<<<ntiles, 544, NODE_SMEM_BYTES>>>(node_attrs, out, N);
}

// round 14
// speedup vs baseline: 3.8629x; 1.0323x over previous
#include <cuda_runtime.h>
#include <cuda_fp16.h>

typedef unsigned long long u64;

#define ATTRC    16
#define RADIALC  8
#define NMAX     10000
#define EMAX     100000

// ---------------------------------------------------------------------------
// Packed f32x2 helpers
// ---------------------------------------------------------------------------
__device__ __forceinline__ u64 fma2(u64 a, u64 b, u64 c) {
    u64 d; asm("fma.rn.f32x2 %0, %1, %2, %3;" : "=l"(d) : "l"(a), "l"(b), "l"(c)); return d;
}
__device__ __forceinline__ u64 splat2(float w) {
    u64 d; unsigned int b = __float_as_uint(w);
    asm("mov.b64 %0, {%1, %1};" : "=l"(d) : "r"(b)); return d;
}
__device__ __forceinline__ float2 unpk(u64 v) {
    unsigned int lo, hi; asm("mov.b64 {%0, %1}, %2;" : "=r"(lo), "=r"(hi) : "l"(v));
    return make_float2(__uint_as_float(lo), __uint_as_float(hi));
}
__device__ __forceinline__ void red_v4(float* p, float a, float b, float c, float d) {
    asm volatile("red.global.add.v4.f32 [%0], {%1, %2, %3, %4};"
                 :: "l"(p), "f"(a), "f"(b), "f"(c), "f"(d) : "memory");
}

// ---------------------------------------------------------------------------
// Device scratch  (g_cnt relies on static zero-init; scan re-zeroes it after
// reading so every graph replay sees zeros again)
// ---------------------------------------------------------------------------
__device__ __align__(16) float  g_WE[32768];          // [k=(r*32+u)][wp][4 blocks]
__device__ __align__(16) float  g_WS[32768];          // [k2=(u*16+v)][wp][2 paths]
__device__ __align__(16) float  g_M[NMAX * 128];      // messages [n][lane][4]=(ms,mv0,mv1,mv2)
__device__ __align__(16) __half g_Q[NMAX * 2048];     // Q[n][g][r][w]  (fp16, 41 MB -> L2-resident)
__device__ int g_cnt[NMAX];
__device__ int g_startArr[NMAX + 1];
__device__ int g_cur[NMAX];
__device__ int g_eidx[EMAX];
__device__ int g_work;                                // work-steal ticket

// ---------------------------------------------------------------------------
// Prep kernel: fold both weight sets + zero M + sender histogram, one launch.
//   c_edge = c_node = 1/128
// ---------------------------------------------------------------------------
__global__ void prep_kernel(const float* __restrict__ Wgen,
                            const float* __restrict__ L1s,
                            const float* __restrict__ L1v,
                            const float* __restrict__ WS0,
                            const float* __restrict__ WS1,
                            const float* __restrict__ L2s,
                            const float* __restrict__ L2v,
                            const int* __restrict__ edge_index,
                            int nM, int E)
{
    int i = blockIdx.x * blockDim.x + threadIdx.x;
    if (i < nM) g_M[i] = 0.f;
    if (i < E)  atomicAdd(&g_cnt[edge_index[i]], 1);   // g_cnt zeroed by scan

    if (i < 32768) {
        {   // fold edge weights
            int b   = i >> 13;
            int rem = i & 8191;
            int r   = rem >> 10;
            int u   = (rem >> 5) & 31;
            int wp  = rem & 31;
            const float* wg = Wgen + r * 4096 + b * 1024 + u * 32;
            const float* L  = (b == 1 || b == 2) ? L1v : L1s;
            float acc = 0.f;
#pragma unroll
            for (int w = 0; w < 32; w++) acc = fmaf(wg[w], L[w * 32 + wp], acc);
            float c = 0.0078125f;
            if (b == 3) c *= 0.57735026918962576f;   // fold 1/sqrt(3) into WD
            g_WE[(r * 32 + u) * 128 + wp * 4 + b] = acc * c;
        }
        {   // fold node weights
            int sb  = i >> 14;
            int rem = i & 16383;
            int uv  = rem >> 5;
            int wp  = rem & 31;
            const float* ws = (sb ? WS1 : WS0) + uv * 32;
            const float* L  = sb ? L2v : L2s;
            float acc = 0.f;
#pragma unroll
            for (int w = 0; w < 32; w++) acc = fmaf(ws[w], L[w * 32 + wp], acc);
            g_WS[uv * 64 + wp * 2 + sb] = acc * 0.0078125f;
        }
    }
}

// ---------------------------------------------------------------------------
// CSR: shfl-based exclusive scan; self-resets g_cnt and g_work.
// ---------------------------------------------------------------------------
__global__ void scan_kernel(int N)
{
    __shared__ int wsum[32];
    __shared__ int wbase[32];
    __shared__ int carry;
    const int tid  = threadIdx.x;
    const int lane = tid & 31;
    const int wid  = tid >> 5;

    if (tid == 0) { carry = 0; g_work = 0; }
    __syncthreads();

    for (int base = 0; base < N; base += 1024) {
        int i = base + tid;
        int v = 0;
        if (i < N) { v = g_cnt[i]; g_cnt[i] = 0; }   // read + reset for next replay
        int x = v;
#pragma unroll
        for (int off = 1; off < 32; off <<= 1) {
            int t = __shfl_up_sync(0xffffffffu, x, off);
            if (lane >= off) x += t;
        }
        if (lane == 31) wsum[wid] = x;
        __syncthreads();

        if (wid == 0) {
            int sv = wsum[lane];
            int y  = sv;
#pragma unroll
            for (int off = 1; off < 32; off <<= 1) {
                int t = __shfl_up_sync(0xffffffffu, y, off);
                if (lane >= off) y += t;
            }
            wbase[lane] = y - sv;
            if (lane == 31) wsum[0] = y;
        }
        __syncthreads();

        int c  = carry;
        int st = c + wbase[wid] + (x - v);
        if (i < N) { g_startArr[i] = st; g_cur[i] = st; }
        __syncthreads();
        if (tid == 0) carry = c + wsum[0];
        __syncthreads();
    }
    if (tid == 0) g_startArr[N] = carry;
}

// ===========================================================================
// Q kernel: Q[n][g][r][w] = sum_u Wg[r][u][w] * x[n][u]  (+ CSR scatter)
// 544 threads, 68-node tiles -> 148 tiles = 1 wave.  Q stored fp16.
// ===========================================================================
#define QTILE 68
#define QROW  68
#define QARR  2176
#define QW_OFF 0
#define QX_OFF 32768
#define Q_SMEM_FLOATS (QX_OFF + 4 * QARR)
#define Q_SMEM_BYTES  (Q_SMEM_FLOATS * 4)

__global__ void __launch_bounds__(544, 1)
q_kernel(const float* __restrict__ node_feats,
         const int* __restrict__ edge_index,
         int N, int E)
{
    extern __shared__ float s[];
    const int tid  = threadIdx.x;
    const int lane = tid & 31;
    const int eo   = tid >> 5;
    const int eb   = eo << 2;

    // CSR scatter (overlaps weight staging)
    for (int i = blockIdx.x * 544 + tid; i < E; i += gridDim.x * 544) {
        int pos = atomicAdd(&g_cur[edge_index[i]], 1);
        g_eidx[pos] = i;
    }

    for (int i = tid; i < 8192; i += 544)
        ((float4*)s)[i] = ((const float4*)g_WE)[i];

    const int ntiles = (N + QTILE - 1) / QTILE;

    for (int t = blockIdx.x; t < ntiles; t += gridDim.x) {
        const int n0 = t * QTILE;
        __syncthreads();

        for (int q = tid; q < QTILE * 128; q += 544) {
            int e = q >> 7, f = q & 127;
            int n = n0 + e;
            float v = (n < N) ? node_feats[(size_t)n * 128 + f] : 0.f;
            if (f < 32) {
                s[QX_OFF + f * QROW + e] = v;
            } else {
                int tt = f - 32;
                int uu = tt / 3;
                int ii = tt - uu * 3;
                s[QX_OFF + (1 + ii) * QARR + uu * QROW + e] = v;
            }
        }
        __syncthreads();

#pragma unroll 1
        for (int r = 0; r < 8; r++) {
            u64 acc[8][2];
#pragma unroll
            for (int g = 0; g < 8; g++) { acc[g][0] = 0ull; acc[g][1] = 0ull; }

            const int wbase2 = (r << 5) * 128 + lane * 4;
#pragma unroll 8
            for (int u = 0; u < 32; u++) {
                float4 wv = *(const float4*)&s[QW_OFF + wbase2 + u * 128];
                u64 wa = splat2(wv.x), wb = splat2(wv.y),
                    wc = splat2(wv.z), wd = splat2(wv.w);
                int xo = u * QROW + eb;
                ulonglong2 xs = *(const ulonglong2*)&s[QX_OFF + 0 * QARR + xo];
                ulonglong2 x0 = *(const ulonglong2*)&s[QX_OFF + 1 * QARR + xo];
                ulonglong2 x1 = *(const ulonglong2*)&s[QX_OFF + 2 * QARR + xo];
                ulonglong2 x2 = *(const ulonglong2*)&s[QX_OFF + 3 * QARR + xo];

                acc[0][0] = fma2(xs.x, wa, acc[0][0]); acc[0][1] = fma2(xs.y, wa, acc[0][1]);
                acc[1][0] = fma2(xs.x, wb, acc[1][0]); acc[1][1] = fma2(xs.y, wb, acc[1][1]);
                acc[2][0] = fma2(x0.x, wc, acc[2][0]); acc[2][1] = fma2(x0.y, wc, acc[2][1]);
                acc[3][0] = fma2(x1.x, wc, acc[3][0]); acc[3][1] = fma2(x1.y, wc, acc[3][1]);
                acc[4][0] = fma2(x2.x, wc, acc[4][0]); acc[4][1] = fma2(x2.y, wc, acc[4][1]);
                acc[5][0] = fma2(x0.x, wd, acc[5][0]); acc[5][1] = fma2(x0.y, wd, acc[5][1]);
                acc[6][0] = fma2(x1.x, wd, acc[6][0]); acc[6][1] = fma2(x1.y, wd, acc[6][1]);
                acc[7][0] = fma2(x2.x, wd, acc[7][0]); acc[7][1] = fma2(x2.y, wd, acc[7][1]);
            }

#pragma unroll
            for (int p = 0; p < 2; p++) {
#pragma unroll
                for (int h = 0; h < 2; h++) {
                    int n = n0 + eb + p * 2 + h;
                    if (n >= N) continue;
                    __half* qn = g_Q + (size_t)n * 2048 + r * 32 + lane;
#pragma unroll
                    for (int g = 0; g < 8; g++) {
                        float2 f2 = unpk(acc[g][p]);
                        qn[g * 256] = __float2half_rn(h ? f2.y : f2.x);
                    }
                }
            }
        }
    }
}

// ===========================================================================
// Edge kernel (CSR, work-stealing, software-pipelined):
//   - warp grabs a sender ticket
//   - per 32-edge chunk: lane i prefetches eidx+receiver (coalesced/gather),
//     broadcast via shfl (kills 2 serial latencies per edge)
//   - edge j+1's attr/feat loads are issued before edge j's compute+red
// ===========================================================================
__global__ void __launch_bounds__(512, 1)
edge_kernel(const float* __restrict__ edge_attrs,
            const float* __restrict__ edge_feats,
            const int*   __restrict__ edge_index,
            int E, int N)
{
    const int lane = threadIdx.x & 31;

    while (true) {
        int n = 0;
        if (lane == 0) n = atomicAdd(&g_work, 1);
        n = __shfl_sync(0xffffffffu, n, 0);
        if (n >= N) break;

        int s0 = g_startArr[n];
        int s1 = g_startArr[n + 1];
        if (s0 == s1) continue;

        const __half* Qn = g_Q + (size_t)n * 2048 + lane;
        float q[8][8];
#pragma unroll
        for (int g = 0; g < 8; g++)
#pragma unroll
            for (int r = 0; r < 8; r++)
                q[g][r] = __half2float(Qn[g * 256 + r * 32]);

        for (int c0 = s0; c0 < s1; c0 += 32) {
            int len = s1 - c0;
            if (len > 32) len = 32;

            // warp-wide prefetch of edge ids + receivers for this chunk
            int eV = 0, rV = 0;
            if (lane < len) {
                eV = __ldg(&g_eidx[c0 + lane]);
                rV = __ldg(&edge_index[E + eV]);
            }

            // prime the pipeline with edge 0's data
            int e0 = __shfl_sync(0xffffffffu, eV, 0);
            float4 ea  = *(const float4*)&edge_attrs[(size_t)e0 * 4];
            float4 ef0 = *(const float4*)&edge_feats[(size_t)e0 * 8];
            float4 ef1 = *(const float4*)&edge_feats[(size_t)e0 * 8 + 4];

            for (int j = 0; j < len; j++) {
                int rcv = __shfl_sync(0xffffffffu, rV, j);

                // issue next edge's loads before current compute
                float4 ea_n = ea, ef0_n = ef0, ef1_n = ef1;
                if (j + 1 < len) {
                    int e2 = __shfl_sync(0xffffffffu, eV, j + 1);
                    ea_n  = *(const float4*)&edge_attrs[(size_t)e2 * 4];
                    ef0_n = *(const float4*)&edge_feats[(size_t)e2 * 8];
                    ef1_n = *(const float4*)&edge_feats[(size_t)e2 * 8 + 4];
                }

                float p[8];
#pragma unroll
                for (int g = 0; g < 8; g++) {
                    float a =        q[g][0] * ef0.x;
                    a = fmaf(q[g][1], ef0.y, a);
                    a = fmaf(q[g][2], ef0.z, a);
                    a = fmaf(q[g][3], ef0.w, a);
                    a = fmaf(q[g][4], ef1.x, a);
                    a = fmaf(q[g][5], ef1.y, a);
                    a = fmaf(q[g][6], ef1.z, a);
                    a = fmaf(q[g][7], ef1.w, a);
                    p[g] = a;
                }

                float ms  = fmaf(p[0], ea.x, fmaf(p[5], ea.y, fmaf(p[6], ea.z, p[7] * ea.w)));
                float mv0 = fmaf(p[1], ea.y, p[2] * ea.x);
                float mv1 = fmaf(p[1], ea.z, p[3] * ea.x);
                float mv2 = fmaf(p[1], ea.w, p[4] * ea.x);

                red_v4(g_M + (size_t)rcv * 128 + lane * 4, ms, mv0, mv1, mv2);

                ea = ea_n; ef0 = ef0_n; ef1 = ef1_n;
            }
        }
    }
}

// ===========================================================================
// Node kernel: 544 threads, 68-node tiles, u-chunk(4) register caching of M.
// ===========================================================================
#define NROW  68
#define NARR  2176
#define NW_OFF  0
#define NMS_OFF 32768
#define NMV_OFF(i) (NMS_OFF + NARR * (1 + (i)))
#define NNA_OFF (NMS_OFF + NARR * 4)
#define NODE_SMEM_FLOATS (NNA_OFF + 16 * NROW)
#define NODE_SMEM_BYTES  (NODE_SMEM_FLOATS * 4)

__global__ void __launch_bounds__(544, 1)
node_kernel(const float* __restrict__ node_attrs,
            float* __restrict__ out,
            int N)
{
    extern __shared__ float s[];
    const int tid  = threadIdx.x;
    const int lane = tid & 31;
    const int eo   = tid >> 5;
    const int eb   = eo << 2;

    for (int i = tid; i < 8192; i += 544)
        ((float4*)s)[i] = ((const float4*)g_WS)[i];

    const int ntiles = (N + QTILE - 1) / QTILE;

    for (int t = blockIdx.x; t < ntiles; t += gridDim.x) {
        const int n0 = t * QTILE;
        __syncthreads();

        // stage M ([n][ln][4] = ms,mv0,mv1,mv2)
        for (int q = tid; q < QTILE * 128; q += 544) {
            int e = q >> 7, f = q & 127;
            int n = n0 + e;
            float v = (n < N) ? g_M[(size_t)n * 128 + f] : 0.f;
            int ln = f >> 2, c = f & 3;
            if (c == 0) s[NMS_OFF + ln * NROW + e] = v;
            else        s[NMV_OFF(c - 1) + ln * NROW + e] = v;
        }
        for (int q = tid; q < QTILE * 16; q += 544) {
            int e = q >> 4, v = q & 15;
            int n = n0 + e;
            s[NNA_OFF + v * NROW + e] = (n < N) ? node_attrs[(size_t)n * 16 + v] : 0.f;
        }
        __syncthreads();

        u64 tot[8];
#pragma unroll
        for (int q = 0; q < 8; q++) tot[q] = 0ull;

#pragma unroll 1
        for (int uc = 0; uc < 32; uc += 4) {
            ulonglong2 mm[4][4];
#pragma unroll
            for (int j = 0; j < 4; j++) {
                int ao = (uc + j) * NROW + eb;
                mm[j][0] = *(const ulonglong2*)&s[NMS_OFF    + ao];
                mm[j][1] = *(const ulonglong2*)&s[NMV_OFF(0) + ao];
                mm[j][2] = *(const ulonglong2*)&s[NMV_OFF(1) + ao];
                mm[j][3] = *(const ulonglong2*)&s[NMV_OFF(2) + ao];
            }

#pragma unroll 1
            for (int v = 0; v < 16; v++) {
                u64 part[8];
#pragma unroll
                for (int q = 0; q < 8; q++) part[q] = 0ull;

#pragma unroll
                for (int j = 0; j < 4; j++) {
                    float2 wv = *(const float2*)&s[NW_OFF + ((uc + j) * 16 + v) * 64 + lane * 2];
                    u64 w0 = splat2(wv.x), w1 = splat2(wv.y);
                    part[0] = fma2(mm[j][0].x, w0, part[0]); part[1] = fma2(mm[j][0].y, w0, part[1]);
                    part[2] = fma2(mm[j][1].x, w1, part[2]); part[3] = fma2(mm[j][1].y, w1, part[3]);
                    part[4] = fma2(mm[j][2].x, w1, part[4]); part[5] = fma2(mm[j][2].y, w1, part[5]);
                    part[6] = fma2(mm[j][3].x, w1, part[6]); part[7] = fma2(mm[j][3].y, w1, part[7]);
                }

                ulonglong2 na = *(const ulonglong2*)&s[NNA_OFF + v * NROW + eb];
#pragma unroll
                for (int q = 0; q < 8; q += 2) {
                    tot[q]     = fma2(na.x, part[q],     tot[q]);
                    tot[q + 1] = fma2(na.y, part[q + 1], tot[q + 1]);
                }
            }
        }

#pragma unroll
        for (int p = 0; p < 2; p++) {
            float2 S  = unpk(tot[0 + p]);
            float2 V0 = unpk(tot[2 + p]);
            float2 V1 = unpk(tot[4 + p]);
            float2 V2 = unpk(tot[6 + p]);
#pragma unroll
            for (int h = 0; h < 2; h++) {
                int e = eb + 2 * p + h;
                int n = n0 + e;
                if (n >= N) continue;
                float* o = out + (size_t)n * 128;
                o[lane]              = s[NMS_OFF    + lane * NROW + e] + (h ? S.y  : S.x);
                o[32 + lane * 3 + 0] = s[NMV_OFF(0) + lane * NROW + e] + (h ? V0.y : V0.x);
                o[32 + lane * 3 + 1] = s[NMV_OFF(1) + lane * NROW + e] + (h ? V1.y : V1.x);
                o[32 + lane * 3 + 2] = s[NMV_OFF(2) + lane * NROW + e] + (h ? V2.y : V2.x);
            }
        }
    }
}

// ===========================================================================
// Launch
// ===========================================================================
extern "C" void kernel_launch(void* const* d_in, const int* in_sizes, int n_in,
                              void* d_out, int out_size)
{
    const float* node_attrs = (const float*)d_in[0];
    const float* node_feats = (const float*)d_in[1];
    const float* edge_attrs = (const float*)d_in[2];
    const float* edge_feats = (const float*)d_in[3];
    const int*   edge_index = (const int*)  d_in[4];
    const float* Wgen       = (const float*)d_in[5];
    const float* L1s        = (const float*)d_in[6];
    const float* L1v        = (const float*)d_in[7];
    const float* WS0        = (const float*)d_in[8];
    const float* WS1        = (const float*)d_in[9];
    const float* L2s        = (const float*)d_in[10];
    const float* L2v        = (const float*)d_in[11];
    float* out = (float*)d_out;

    const int N = in_sizes[0] / ATTRC;        // 10000
    const int E = in_sizes[3] / RADIALC;      // 100000
    const int ntiles = (N + QTILE - 1) / QTILE;   // 148

    cudaFuncSetAttribute(q_kernel,    cudaFuncAttributeMaxDynamicSharedMemorySize, Q_SMEM_BYTES);
    cudaFuncSetAttribute(node_kernel, cudaFuncAttributeMaxDynamicSharedMemorySize, NODE_SMEM_BYTES);

    prep_kernel<<<(N * 128 + 511) / 512, 512>>>(Wgen, L1s, L1v, WS0, WS1, L2s, L2v,
                                                edge_index, N * 128, E);
    scan_kernel<<<1, 1024>>>(N);
    q_kernel<<<ntiles, 544, Q_SMEM_BYTES>>>(node_feats, edge_index, N, E);
    edge_kernel<<<148, 512>>>(edge_attrs, edge_feats, edge_index, E, N);
    node_kernel<<<ntiles, 544, NODE_SMEM_BYTES>>>(node_attrs, out, N);
}